// round 8
// baseline (speedup 1.0000x reference)
#include <cuda_runtime.h>

#define NP 8192
#define NQ (2*NP)

__device__ __align__(16) float g_U[NQ*128];
__device__ float g_cmin[NQ*16];
__device__ unsigned long long g_surv[(long)NQ*128];
__device__ int   g_qcnt[NQ];
__device__ int   g_knn[NQ*16];
__device__ __align__(16) float g_wu [64*128];
__device__ __align__(16) float g_w1t[64*64];
__device__ __align__(16) float g_w2t[64*128];

__device__ __forceinline__ float leaky(float v){ return fmaxf(v, 0.2f*v); }
__device__ __forceinline__ float distp(float xi,float yi,float zi,const float4 c){
    return fmaf(zi,c.z,fmaf(yi,c.y,fmaf(xi,c.x,c.w)));
}
__device__ __forceinline__ unsigned int okey(float d){
    unsigned int u = __float_as_uint(d);
    u ^= ((unsigned int)((int)u >> 31)) | 0x80000000u;
    return u;
}
__device__ __forceinline__ unsigned long long umin64(unsigned long long a, unsigned long long b){
    return a < b ? a : b;
}

// ---------------- prep: transpose weights + zero counters ----------------
__global__ void prep_kernel(const float* __restrict__ Wn, const float* __restrict__ We,
                            const float* __restrict__ W1, const float* __restrict__ W2){
    int i = blockIdx.x*blockDim.x + threadIdx.x;
    if (i < NQ) g_qcnt[i] = 0;
    if (i < 8192){
        int c = i >> 7, o = i & 127;
        g_wu[i] = (o < 64) ? Wn[o*64 + c] : We[(o-64)*64 + c];
    } else if (i < 12288){
        int j = i - 8192; int c = j >> 6, o = j & 63;
        g_w1t[j] = W1[o*64 + c];
    } else if (i < 20480){
        int j = i - 12288; int c = j >> 7, o = j & 127;
        g_w2t[j] = W2[o*64 + c];
    }
}

// ---------- KNN pass 1: branchless chunk-mins, thread = (query, quarter of 2048) ----------
__global__ void knn_pass1(const float* __restrict__ pos){
    __shared__ float4 tile[256];
    int bx = blockIdx.x;
    int b  = bx >> 7;
    int r  = bx & 127;
    int quarter = r >> 5;
    int n  = (r & 31)*256 + threadIdx.x;
    const float* pb = pos + b*NP*3;
    float xi = pb[n*3+0], yi = pb[n*3+1], zi = pb[n*3+2];
    long obase = ((long)(b*NP + n))*16 + quarter*4;

#pragma unroll
    for (int c4 = 0; c4 < 4; c4++){
        float mA = 3.4e38f, mB = 3.4e38f;
#pragma unroll
        for (int t2 = 0; t2 < 2; t2++){
            int jb = quarter*2048 + c4*512 + t2*256;
            int j  = jb + threadIdx.x;
            float x = pb[j*3+0], y = pb[j*3+1], z = pb[j*3+2];
            float sq = x*x; sq = fmaf(y,y,sq); sq = fmaf(z,z,sq);
            __syncthreads();
            tile[threadIdx.x] = make_float4(-2.0f*x, -2.0f*y, -2.0f*z, sq);
            __syncthreads();
#pragma unroll 8
            for (int jj = 0; jj < 256; jj += 4){
                float d0 = distp(xi,yi,zi, tile[jj+0]);
                float d1 = distp(xi,yi,zi, tile[jj+1]);
                float d2 = distp(xi,yi,zi, tile[jj+2]);
                float d3 = distp(xi,yi,zi, tile[jj+3]);
                mA = fminf(mA, fminf(d0,d1));
                mB = fminf(mB, fminf(d2,d3));
            }
        }
        g_cmin[obase + c4] = fminf(mA, mB);
    }
}

// ---------- KNN pass 2: filtered scan, atomic append to per-query list ----------
__global__ void knn_pass2(const float* __restrict__ pos){
    __shared__ float4 tile[256];
    int bx  = blockIdx.x;             // 512 blocks
    int seg = bx & 7;
    int q   = (bx >> 3)*256 + threadIdx.x;
    int b   = q >> 13;
    int n   = q & 8191;
    const float* pb = pos + b*NP*3;
    float xi = pb[n*3+0], yi = pb[n*3+1], zi = pb[n*3+2];

    float T0 = -3.4e38f;
#pragma unroll
    for (int s = 0; s < 16; s++) T0 = fmaxf(T0, g_cmin[(long)q*16 + s]);

#pragma unroll
    for (int t = 0; t < 4; t++){
        int jb = seg*1024 + t*256;
        int j  = jb + threadIdx.x;
        float x = pb[j*3+0], y = pb[j*3+1], z = pb[j*3+2];
        float sq = x*x; sq = fmaf(y,y,sq); sq = fmaf(z,z,sq);
        __syncthreads();
        tile[threadIdx.x] = make_float4(-2.0f*x, -2.0f*y, -2.0f*z, sq);
        __syncthreads();
        for (int jj = 0; jj < 256; jj += 4){
            float d0 = distp(xi,yi,zi, tile[jj+0]);
            float d1 = distp(xi,yi,zi, tile[jj+1]);
            float d2 = distp(xi,yi,zi, tile[jj+2]);
            float d3 = distp(xi,yi,zi, tile[jj+3]);
            float mn = fminf(fminf(d0,d1), fminf(d2,d3));
            if (mn <= T0){
                float dd[4] = {d0,d1,d2,d3};
#pragma unroll
                for (int u = 0; u < 4; u++){
                    if (dd[u] <= T0){
                        int slot = atomicAdd(&g_qcnt[q], 1);
                        if (slot < 128)
                            g_surv[(long)q*128 + slot] =
                                ((unsigned long long)okey(dd[u]) << 32) | (unsigned int)(jb + jj + u);
                    }
                }
            }
        }
    }
}

// ---------- KNN pass 3: warp/query, register keys, 16 warp-min rounds ----------
__global__ void knn_pass3(const float* __restrict__ pos){
    int w    = threadIdx.x >> 5;
    int lane = threadIdx.x & 31;
    int q    = blockIdx.x*8 + w;       // 2048 blocks x 8 warps

    int cnt = g_qcnt[q];
    if (cnt <= 128){
        unsigned long long k[4];
#pragma unroll
        for (int u = 0; u < 4; u++){
            int t = lane + u*32;
            k[u] = (t < cnt) ? g_surv[(long)q*128 + t] : ~0ull;
        }
        for (int r = 0; r < 16; r++){
            unsigned long long best = umin64(umin64(k[0],k[1]), umin64(k[2],k[3]));
            unsigned long long rb = best;
#pragma unroll
            for (int o = 16; o; o >>= 1)
                rb = umin64(rb, __shfl_down_sync(0xffffffff, rb, o));
            rb = __shfl_sync(0xffffffff, rb, 0);
            if (lane == 0) g_knn[(long)q*16 + r] = (int)(rb & 0xffffffffull);
            if (best == rb){
#pragma unroll
                for (int u = 0; u < 4; u++) if (k[u] == rb) k[u] = ~0ull;
            }
        }
    } else if (lane == 0){
        // exact full rescan fallback (statistically never taken)
        int b = q >> 13, n = q & 8191;
        const float* pb = pos + b*NP*3;
        float xi = pb[n*3+0], yi = pb[n*3+1], zi = pb[n*3+2];
        unsigned long long bk[16];
#pragma unroll
        for (int s = 0; s < 16; s++) bk[s] = ~0ull;
        unsigned long long worst = ~0ull; int ws = 0;
        for (int j = 0; j < NP; j++){
            float x = pb[j*3+0], y = pb[j*3+1], z = pb[j*3+2];
            float sq = x*x; sq = fmaf(y,y,sq); sq = fmaf(z,z,sq);
            float d = fmaf(zi,-2.0f*z, fmaf(yi,-2.0f*y, fmaf(xi,-2.0f*x, sq)));
            unsigned long long key = ((unsigned long long)okey(d) << 32) | (unsigned int)j;
            if (key < worst){
                bk[ws] = key;
                worst = bk[0]; ws = 0;
                for (int s = 1; s < 16; s++) if (bk[s] > worst){ worst = bk[s]; ws = s; }
            }
        }
        for (int rr = 0; rr < 16; rr++){
            unsigned long long best = ~0ull; int bj = 0;
            for (int s = 0; s < 16; s++) if (bk[s] < best){ best = bk[s]; bj = s; }
            bk[bj] = ~0ull;
            g_knn[(long)q*16 + rr] = (int)(best & 0xffffffffull);
        }
    }
}

// ---------------- U = [W_node; W_edge] * feat ----------------
__global__ void u_kernel(const float* __restrict__ feat){
    extern __shared__ float smC[];
    float* fs = smC;
    float* ws = smC + 64*128;
    int q0 = blockIdx.x*128;
    int b  = q0 >> 13;
    int n0 = q0 & 8191;
    for (int i=threadIdx.x; i<64*128; i+=256){
        int c = i>>7, nn = i&127;
        fs[i] = feat[((long)(b*64 + c))*NP + n0 + nn];
        ws[i] = g_wu[i];
    }
    __syncthreads();
    int tx = threadIdx.x & 15, ty = threadIdx.x >> 4;
    float acc[8][8];
#pragma unroll
    for (int i=0;i<8;i++)
#pragma unroll
        for (int j=0;j<8;j++) acc[i][j]=0.f;
#pragma unroll 4
    for (int c=0;c<64;c++){
        float4 a0 = *(const float4*)&fs[c*128 + ty*8];
        float4 a1 = *(const float4*)&fs[c*128 + ty*8 + 4];
        float4 w0 = *(const float4*)&ws[c*128 + tx*8];
        float4 w1 = *(const float4*)&ws[c*128 + tx*8 + 4];
        float av[8] = {a0.x,a0.y,a0.z,a0.w,a1.x,a1.y,a1.z,a1.w};
        float bv[8] = {w0.x,w0.y,w0.z,w0.w,w1.x,w1.y,w1.z,w1.w};
#pragma unroll
        for (int i=0;i<8;i++)
#pragma unroll
            for (int j=0;j<8;j++) acc[i][j] = fmaf(av[i], bv[j], acc[i][j]);
    }
#pragma unroll
    for (int i=0;i<8;i++){
        long q = q0 + ty*8 + i;
        float* r = &g_U[q*128 + tx*8];
        *(float4*)r     = make_float4(acc[i][0],acc[i][1],acc[i][2],acc[i][3]);
        *(float4*)(r+4) = make_float4(acc[i][4],acc[i][5],acc[i][6],acc[i][7]);
    }
}

// ---------------- fused gather + h1 + m1 + m2 + maxpool (FFMA, 96KB smem) ----------------
__global__ void __launch_bounds__(256, 2)
edge_main(const float* __restrict__ bn,  const float* __restrict__ be,
          const float* __restrict__ vb1, const float* __restrict__ vb2,
          float* __restrict__ out){
    extern __shared__ float sm[];
    float* h1T = sm;                  // [64][136], reused as h2T
    float* w1s = h1T + 64*136;
    float* w2s = w1s + 64*64;
    float* uec = w2s + 64*128;
    float* red = uec + 512;
    float* bns = red + 2048;
    float* bes = bns + 64;
    float* b1s = bes + 64;
    float* b2s = b1s + 64;
    int*   idxs = (int*)(b2s + 128);

    int q0 = blockIdx.x*8;
    int b  = q0 >> 13;
    int n0 = q0 & 8191;
    int tid = threadIdx.x;

    for (int i=tid;i<4096;i+=256) w1s[i] = g_w1t[i];
    for (int i=tid;i<8192;i+=256) w2s[i] = g_w2t[i];
    if (tid<64){ bns[tid]=bn[tid]; bes[tid]=be[tid]; b1s[tid]=vb1[tid]; }
    if (tid<128) b2s[tid]=vb2[tid];
    if (tid<128) idxs[tid] = g_knn[(long)q0*16 + tid];
    for (int i=tid;i<512;i+=256){ int p=i>>6, j=i&63; uec[i] = g_U[(long)(q0+p)*128 + 64 + j]; }
    __syncthreads();

    { // stage A: gather + layer1 -> h1T[j][m]
        int m  = tid >> 1;
        int jb = (tid & 1) * 32;
        int p  = m >> 4;
        int nb = idxs[m];
        const float* Ur = &g_U[(long)((b<<13) + nb)*128];
#pragma unroll
        for (int v=0; v<8; v++){
            float4 un = *(const float4*)&Ur[jb + v*4];
            float4 ue = *(const float4*)&Ur[64 + jb + v*4];
            float unv[4] = {un.x,un.y,un.z,un.w};
            float uev[4] = {ue.x,ue.y,ue.z,ue.w};
#pragma unroll
            for (int e=0;e<4;e++){
                int j = jb + v*4 + e;
                float a = leaky(unv[e] + bns[j]);
                float c = leaky(uev[e] - uec[p*64 + j] + bes[j]);
                h1T[j*136 + m] = a + c;
            }
        }
    }
    __syncthreads();

    int tx = tid & 15, ty = tid >> 4;

    { // stage B: M=128 N=64 K=64, FFMA
        float acc[8][4];
#pragma unroll
        for (int i=0;i<8;i++)
#pragma unroll
            for (int o=0;o<4;o++) acc[i][o]=0.f;
#pragma unroll 4
        for (int c=0;c<64;c++){
            float4 a0 = *(const float4*)&h1T[c*136 + ty*8];
            float4 a1 = *(const float4*)&h1T[c*136 + ty*8 + 4];
            float4 wv = *(const float4*)&w1s[c*64 + tx*4];
            float av[8] = {a0.x,a0.y,a0.z,a0.w,a1.x,a1.y,a1.z,a1.w};
            float bb[4] = {wv.x,wv.y,wv.z,wv.w};
#pragma unroll
            for (int i=0;i<8;i++)
#pragma unroll
                for (int o=0;o<4;o++) acc[i][o] = fmaf(av[i], bb[o], acc[i][o]);
        }
        __syncthreads();
#pragma unroll
        for (int i=0;i<8;i++){
            int m = ty*8 + i;
#pragma unroll
            for (int o=0;o<4;o++)
                h1T[(tx*4+o)*136 + m] = leaky(acc[i][o] + b1s[tx*4+o]);
        }
    }
    __syncthreads();

    { // stage C: M=128 N=128 K=64, FFMA + partial max
        float acc[8][8];
#pragma unroll
        for (int i=0;i<8;i++)
#pragma unroll
            for (int o=0;o<8;o++) acc[i][o]=0.f;
#pragma unroll 4
        for (int c=0;c<64;c++){
            float4 a0 = *(const float4*)&h1T[c*136 + ty*8];
            float4 a1 = *(const float4*)&h1T[c*136 + ty*8 + 4];
            float4 w0 = *(const float4*)&w2s[c*128 + tx*8];
            float4 w1 = *(const float4*)&w2s[c*128 + tx*8 + 4];
            float av[8] = {a0.x,a0.y,a0.z,a0.w,a1.x,a1.y,a1.z,a1.w};
            float bb[8] = {w0.x,w0.y,w0.z,w0.w,w1.x,w1.y,w1.z,w1.w};
#pragma unroll
            for (int i=0;i<8;i++)
#pragma unroll
                for (int o=0;o<8;o++) acc[i][o] = fmaf(av[i], bb[o], acc[i][o]);
        }
#pragma unroll
        for (int o=0;o<8;o++){
            float bias = b2s[tx*8+o];
            float pm = -3.4e38f;
#pragma unroll
            for (int i=0;i<8;i++)
                pm = fmaxf(pm, leaky(acc[i][o] + bias));
            red[ty*128 + tx*8 + o] = pm;
        }
    }
    __syncthreads();

    for (int e=tid; e<1024; e+=256){
        int o = e & 127;
        int p = e >> 7;
        float v = fmaxf(red[(2*p)*128 + o], red[(2*p+1)*128 + o]);
        out[((long)(b*128 + o))*NP + n0 + p] = v;
    }
}

extern "C" void kernel_launch(void* const* d_in, const int* in_sizes, int n_in,
                              void* d_out, int out_size){
    const float* feat = (const float*)d_in[0];
    const float* pos  = (const float*)d_in[1];
    const float* Wn   = (const float*)d_in[2];
    const float* bn   = (const float*)d_in[3];
    const float* We   = (const float*)d_in[4];
    const float* be   = (const float*)d_in[5];
    const float* W1   = (const float*)d_in[6];
    const float* b1   = (const float*)d_in[7];
    const float* W2   = (const float*)d_in[8];
    const float* b2   = (const float*)d_in[9];
    float* out = (float*)d_out;

    cudaFuncSetAttribute(u_kernel,  cudaFuncAttributeMaxDynamicSharedMemorySize, 65536);
    cudaFuncSetAttribute(edge_main, cudaFuncAttributeMaxDynamicSharedMemorySize, 98304);

    prep_kernel<<<80,256>>>(Wn, We, W1, W2);
    knn_pass1<<<256,256>>>(pos);
    knn_pass2<<<512,256>>>(pos);
    knn_pass3<<<2048,256>>>(pos);
    u_kernel<<<128,256,65536>>>(feat);
    edge_main<<<2048,256,96000>>>(bn, be, b1, b2, out);
}

// round 9
// speedup vs baseline: 1.0514x; 1.0514x over previous
#include <cuda_runtime.h>

#define NP 8192
#define NQ (2*NP)

__device__ __align__(16) float g_U[NQ*128];
__device__ float g_cmin[NQ*16];
__device__ unsigned long long g_surv[(long)NQ*8*64];
__device__ int   g_scnt[NQ*8];
__device__ int   g_knn[NQ*16];
__device__ __align__(16) float g_wu [64*128];
__device__ __align__(16) float g_w1t[64*64];
__device__ __align__(16) float g_w2t[64*128];

__device__ __forceinline__ float leaky(float v){ return fmaxf(v, 0.2f*v); }
__device__ __forceinline__ float distp(float xi,float yi,float zi,const float4 c){
    return fmaf(zi,c.z,fmaf(yi,c.y,fmaf(xi,c.x,c.w)));
}
__device__ __forceinline__ unsigned int okey(float d){
    unsigned int u = __float_as_uint(d);
    u ^= ((unsigned int)((int)u >> 31)) | 0x80000000u;
    return u;
}
__device__ __forceinline__ unsigned long long umin64(unsigned long long a, unsigned long long b){
    return a < b ? a : b;
}

// ---------------- prep: transpose weights once ----------------
__global__ void prep_kernel(const float* __restrict__ Wn, const float* __restrict__ We,
                            const float* __restrict__ W1, const float* __restrict__ W2){
    int i = blockIdx.x*blockDim.x + threadIdx.x;
    if (i < 8192){
        int c = i >> 7, o = i & 127;
        g_wu[i] = (o < 64) ? Wn[o*64 + c] : We[(o-64)*64 + c];
    } else if (i < 12288){
        int j = i - 8192; int c = j >> 6, o = j & 63;
        g_w1t[j] = W1[o*64 + c];
    } else if (i < 20480){
        int j = i - 12288; int c = j >> 7, o = j & 127;
        g_w2t[j] = W2[o*64 + c];
    }
}

// ---------- KNN pass 1: branchless chunk-mins, thread = (query, quarter of 2048) ----------
__global__ void knn_pass1(const float* __restrict__ pos){
    __shared__ float4 tile[256];
    int bx = blockIdx.x;
    int b  = bx >> 7;
    int r  = bx & 127;
    int quarter = r >> 5;
    int n  = (r & 31)*256 + threadIdx.x;
    const float* pb = pos + b*NP*3;
    float xi = pb[n*3+0], yi = pb[n*3+1], zi = pb[n*3+2];
    long obase = ((long)(b*NP + n))*16 + quarter*4;

#pragma unroll
    for (int c4 = 0; c4 < 4; c4++){
        float mA = 3.4e38f, mB = 3.4e38f;
#pragma unroll
        for (int t2 = 0; t2 < 2; t2++){
            int jb = quarter*2048 + c4*512 + t2*256;
            int j  = jb + threadIdx.x;
            float x = pb[j*3+0], y = pb[j*3+1], z = pb[j*3+2];
            float sq = x*x; sq = fmaf(y,y,sq); sq = fmaf(z,z,sq);
            __syncthreads();
            tile[threadIdx.x] = make_float4(-2.0f*x, -2.0f*y, -2.0f*z, sq);
            __syncthreads();
#pragma unroll 8
            for (int jj = 0; jj < 256; jj += 4){
                float d0 = distp(xi,yi,zi, tile[jj+0]);
                float d1 = distp(xi,yi,zi, tile[jj+1]);
                float d2 = distp(xi,yi,zi, tile[jj+2]);
                float d3 = distp(xi,yi,zi, tile[jj+3]);
                mA = fminf(mA, fminf(d0,d1));
                mB = fminf(mB, fminf(d2,d3));
            }
        }
        g_cmin[obase + c4] = fminf(mA, mB);
    }
}

// ---------- KNN pass 2: filtered scan, PRIVATE per-(q,seg) buffers (no atomics) ----------
__global__ void knn_pass2(const float* __restrict__ pos){
    __shared__ float4 tile[256];
    int bx  = blockIdx.x;             // 512 blocks
    int seg = bx & 7;
    int q   = (bx >> 3)*256 + threadIdx.x;
    int b   = q >> 13;
    int n   = q & 8191;
    const float* pb = pos + b*NP*3;
    float xi = pb[n*3+0], yi = pb[n*3+1], zi = pb[n*3+2];

    float T0 = -3.4e38f;
#pragma unroll
    for (int s = 0; s < 16; s++) T0 = fmaxf(T0, g_cmin[(long)q*16 + s]);

    unsigned long long* sv = &g_surv[((long)q*8 + seg)*64];
    int c = 0;
#pragma unroll
    for (int t = 0; t < 4; t++){
        int jb = seg*1024 + t*256;
        int j  = jb + threadIdx.x;
        float x = pb[j*3+0], y = pb[j*3+1], z = pb[j*3+2];
        float sq = x*x; sq = fmaf(y,y,sq); sq = fmaf(z,z,sq);
        __syncthreads();
        tile[threadIdx.x] = make_float4(-2.0f*x, -2.0f*y, -2.0f*z, sq);
        __syncthreads();
        for (int jj = 0; jj < 256; jj += 4){
            float d0 = distp(xi,yi,zi, tile[jj+0]);
            float d1 = distp(xi,yi,zi, tile[jj+1]);
            float d2 = distp(xi,yi,zi, tile[jj+2]);
            float d3 = distp(xi,yi,zi, tile[jj+3]);
            float mn = fminf(fminf(d0,d1), fminf(d2,d3));
            if (mn <= T0){
                float dd[4] = {d0,d1,d2,d3};
#pragma unroll
                for (int u = 0; u < 4; u++){
                    if (dd[u] <= T0 && c < 64){
                        sv[c] = ((unsigned long long)okey(dd[u]) << 32) | (unsigned int)(jb + jj + u);
                        c++;
                    }
                }
            }
        }
    }
    g_scnt[(long)q*8 + seg] = c;
}

// ---------- KNN pass 3: warp/query, register keys, 16 warp-min rounds ----------
__global__ void knn_pass3(const float* __restrict__ pos){
    int w    = threadIdx.x >> 5;
    int lane = threadIdx.x & 31;
    int q    = blockIdx.x*8 + w;       // 2048 blocks x 8 warps

    int cs = (lane < 8) ? g_scnt[(long)q*8 + lane] : 0;
    unsigned ovfm = __ballot_sync(0xffffffff, lane < 8 && cs >= 64);
    int pre = cs;
#pragma unroll
    for (int o = 1; o < 8; o <<= 1){
        int v = __shfl_up_sync(0xffffffff, pre, o);
        if (lane >= o) pre += v;
    }
    int ip[8];
#pragma unroll
    for (int s = 0; s < 8; s++) ip[s] = __shfl_sync(0xffffffff, pre, s);
    int ctot = ip[7];

    if (!ovfm && ctot <= 128){
        unsigned long long k[4];
#pragma unroll
        for (int u = 0; u < 4; u++){
            int t = lane + u*32;
            unsigned long long key = ~0ull;
            if (t < ctot){
                int s = 0, base = 0;
#pragma unroll
                for (int kk = 0; kk < 7; kk++){
                    if (t >= ip[kk]){ s = kk+1; base = ip[kk]; }
                }
                key = g_surv[((long)q*8 + s)*64 + (t - base)];
            }
            k[u] = key;
        }
        for (int r = 0; r < 16; r++){
            unsigned long long best = umin64(umin64(k[0],k[1]), umin64(k[2],k[3]));
            unsigned long long rb = best;
#pragma unroll
            for (int o = 16; o; o >>= 1)
                rb = umin64(rb, __shfl_down_sync(0xffffffff, rb, o));
            rb = __shfl_sync(0xffffffff, rb, 0);
            if (lane == 0) g_knn[(long)q*16 + r] = (int)(rb & 0xffffffffull);
            if (best == rb){
#pragma unroll
                for (int u = 0; u < 4; u++) if (k[u] == rb) k[u] = ~0ull;
            }
        }
    } else if (lane == 0){
        // exact full rescan fallback (statistically never taken)
        int b = q >> 13, n = q & 8191;
        const float* pb = pos + b*NP*3;
        float xi = pb[n*3+0], yi = pb[n*3+1], zi = pb[n*3+2];
        unsigned long long bk[16];
#pragma unroll
        for (int s = 0; s < 16; s++) bk[s] = ~0ull;
        unsigned long long worst = ~0ull; int ws = 0;
        for (int j = 0; j < NP; j++){
            float x = pb[j*3+0], y = pb[j*3+1], z = pb[j*3+2];
            float sq = x*x; sq = fmaf(y,y,sq); sq = fmaf(z,z,sq);
            float d = fmaf(zi,-2.0f*z, fmaf(yi,-2.0f*y, fmaf(xi,-2.0f*x, sq)));
            unsigned long long key = ((unsigned long long)okey(d) << 32) | (unsigned int)j;
            if (key < worst){
                bk[ws] = key;
                worst = bk[0]; ws = 0;
                for (int s = 1; s < 16; s++) if (bk[s] > worst){ worst = bk[s]; ws = s; }
            }
        }
        for (int rr = 0; rr < 16; rr++){
            unsigned long long best = ~0ull; int bj = 0;
            for (int s = 0; s < 16; s++) if (bk[s] < best){ best = bk[s]; bj = s; }
            bk[bj] = ~0ull;
            g_knn[(long)q*16 + rr] = (int)(best & 0xffffffffull);
        }
    }
}

// ---------------- U = [W_node; W_edge] * feat ----------------
__global__ void u_kernel(const float* __restrict__ feat){
    extern __shared__ float smC[];
    float* fs = smC;
    float* ws = smC + 64*128;
    int q0 = blockIdx.x*128;
    int b  = q0 >> 13;
    int n0 = q0 & 8191;
    for (int i=threadIdx.x; i<64*128; i+=256){
        int c = i>>7, nn = i&127;
        fs[i] = feat[((long)(b*64 + c))*NP + n0 + nn];
        ws[i] = g_wu[i];
    }
    __syncthreads();
    int tx = threadIdx.x & 15, ty = threadIdx.x >> 4;
    float acc[8][8];
#pragma unroll
    for (int i=0;i<8;i++)
#pragma unroll
        for (int j=0;j<8;j++) acc[i][j]=0.f;
#pragma unroll 4
    for (int c=0;c<64;c++){
        float4 a0 = *(const float4*)&fs[c*128 + ty*8];
        float4 a1 = *(const float4*)&fs[c*128 + ty*8 + 4];
        float4 w0 = *(const float4*)&ws[c*128 + tx*8];
        float4 w1 = *(const float4*)&ws[c*128 + tx*8 + 4];
        float av[8] = {a0.x,a0.y,a0.z,a0.w,a1.x,a1.y,a1.z,a1.w};
        float bv[8] = {w0.x,w0.y,w0.z,w0.w,w1.x,w1.y,w1.z,w1.w};
#pragma unroll
        for (int i=0;i<8;i++)
#pragma unroll
            for (int j=0;j<8;j++) acc[i][j] = fmaf(av[i], bv[j], acc[i][j]);
    }
#pragma unroll
    for (int i=0;i<8;i++){
        long q = q0 + ty*8 + i;
        float* r = &g_U[q*128 + tx*8];
        *(float4*)r     = make_float4(acc[i][0],acc[i][1],acc[i][2],acc[i][3]);
        *(float4*)(r+4) = make_float4(acc[i][4],acc[i][5],acc[i][6],acc[i][7]);
    }
}

// ---------------- fused gather + h1 + m1 + m2 + maxpool (FFMA, 96KB smem) ----------------
__global__ void edge_main(const float* __restrict__ bn,  const float* __restrict__ be,
                          const float* __restrict__ vb1, const float* __restrict__ vb2,
                          float* __restrict__ out){
    extern __shared__ float sm[];
    float* h1T = sm;                  // [64][136], reused as h2T
    float* w1s = h1T + 64*136;
    float* w2s = w1s + 64*64;
    float* uec = w2s + 64*128;
    float* red = uec + 512;
    float* bns = red + 2048;
    float* bes = bns + 64;
    float* b1s = bes + 64;
    float* b2s = b1s + 64;
    int*   idxs = (int*)(b2s + 128);

    int q0 = blockIdx.x*8;
    int b  = q0 >> 13;
    int n0 = q0 & 8191;
    int tid = threadIdx.x;

    for (int i=tid;i<4096;i+=256) w1s[i] = g_w1t[i];
    for (int i=tid;i<8192;i+=256) w2s[i] = g_w2t[i];
    if (tid<64){ bns[tid]=bn[tid]; bes[tid]=be[tid]; b1s[tid]=vb1[tid]; }
    if (tid<128) b2s[tid]=vb2[tid];
    if (tid<128) idxs[tid] = g_knn[(long)q0*16 + tid];
    for (int i=tid;i<512;i+=256){ int p=i>>6, j=i&63; uec[i] = g_U[(long)(q0+p)*128 + 64 + j]; }
    __syncthreads();

    { // stage A: gather + layer1 -> h1T[j][m]
        int m  = tid >> 1;
        int jb = (tid & 1) * 32;
        int p  = m >> 4;
        int nb = idxs[m];
        const float* Ur = &g_U[(long)((b<<13) + nb)*128];
#pragma unroll
        for (int v=0; v<8; v++){
            float4 un = *(const float4*)&Ur[jb + v*4];
            float4 ue = *(const float4*)&Ur[64 + jb + v*4];
            float unv[4] = {un.x,un.y,un.z,un.w};
            float uev[4] = {ue.x,ue.y,ue.z,ue.w};
#pragma unroll
            for (int e=0;e<4;e++){
                int j = jb + v*4 + e;
                float a = leaky(unv[e] + bns[j]);
                float c = leaky(uev[e] - uec[p*64 + j] + bes[j]);
                h1T[j*136 + m] = a + c;
            }
        }
    }
    __syncthreads();

    int tx = tid & 15, ty = tid >> 4;

    { // stage B: M=128 N=64 K=64
        float acc[8][4];
#pragma unroll
        for (int i=0;i<8;i++)
#pragma unroll
            for (int o=0;o<4;o++) acc[i][o]=0.f;
#pragma unroll 4
        for (int c=0;c<64;c++){
            float4 a0 = *(const float4*)&h1T[c*136 + ty*8];
            float4 a1 = *(const float4*)&h1T[c*136 + ty*8 + 4];
            float4 wv = *(const float4*)&w1s[c*64 + tx*4];
            float av[8] = {a0.x,a0.y,a0.z,a0.w,a1.x,a1.y,a1.z,a1.w};
            float bb[4] = {wv.x,wv.y,wv.z,wv.w};
#pragma unroll
            for (int i=0;i<8;i++)
#pragma unroll
                for (int o=0;o<4;o++) acc[i][o] = fmaf(av[i], bb[o], acc[i][o]);
        }
        __syncthreads();
#pragma unroll
        for (int i=0;i<8;i++){
            int m = ty*8 + i;
#pragma unroll
            for (int o=0;o<4;o++)
                h1T[(tx*4+o)*136 + m] = leaky(acc[i][o] + b1s[tx*4+o]);
        }
    }
    __syncthreads();

    { // stage C: M=128 N=128 K=64 + partial max
        float acc[8][8];
#pragma unroll
        for (int i=0;i<8;i++)
#pragma unroll
            for (int o=0;o<8;o++) acc[i][o]=0.f;
#pragma unroll 4
        for (int c=0;c<64;c++){
            float4 a0 = *(const float4*)&h1T[c*136 + ty*8];
            float4 a1 = *(const float4*)&h1T[c*136 + ty*8 + 4];
            float4 w0 = *(const float4*)&w2s[c*128 + tx*8];
            float4 w1 = *(const float4*)&w2s[c*128 + tx*8 + 4];
            float av[8] = {a0.x,a0.y,a0.z,a0.w,a1.x,a1.y,a1.z,a1.w};
            float bb[8] = {w0.x,w0.y,w0.z,w0.w,w1.x,w1.y,w1.z,w1.w};
#pragma unroll
            for (int i=0;i<8;i++)
#pragma unroll
                for (int o=0;o<8;o++) acc[i][o] = fmaf(av[i], bb[o], acc[i][o]);
        }
#pragma unroll
        for (int o=0;o<8;o++){
            float bias = b2s[tx*8+o];
            float pm = -3.4e38f;
#pragma unroll
            for (int i=0;i<8;i++)
                pm = fmaxf(pm, leaky(acc[i][o] + bias));
            red[ty*128 + tx*8 + o] = pm;
        }
    }
    __syncthreads();

    for (int e=tid; e<1024; e+=256){
        int o = e & 127;
        int p = e >> 7;
        float v = fmaxf(red[(2*p)*128 + o], red[(2*p+1)*128 + o]);
        out[((long)(b*128 + o))*NP + n0 + p] = v;
    }
}

extern "C" void kernel_launch(void* const* d_in, const int* in_sizes, int n_in,
                              void* d_out, int out_size){
    const float* feat = (const float*)d_in[0];
    const float* pos  = (const float*)d_in[1];
    const float* Wn   = (const float*)d_in[2];
    const float* bn   = (const float*)d_in[3];
    const float* We   = (const float*)d_in[4];
    const float* be   = (const float*)d_in[5];
    const float* W1   = (const float*)d_in[6];
    const float* b1   = (const float*)d_in[7];
    const float* W2   = (const float*)d_in[8];
    const float* b2   = (const float*)d_in[9];
    float* out = (float*)d_out;

    cudaFuncSetAttribute(u_kernel,  cudaFuncAttributeMaxDynamicSharedMemorySize, 65536);
    cudaFuncSetAttribute(edge_main, cudaFuncAttributeMaxDynamicSharedMemorySize, 98304);

    prep_kernel<<<80,256>>>(Wn, We, W1, W2);
    knn_pass1<<<256,256>>>(pos);
    knn_pass2<<<512,256>>>(pos);
    knn_pass3<<<2048,256>>>(pos);
    u_kernel<<<128,256,65536>>>(feat);
    edge_main<<<2048,256,96000>>>(bn, be, b1, b2, out);
}

// round 10
// speedup vs baseline: 3.4290x; 3.2613x over previous
#include <cuda_runtime.h>

#define NP 8192
#define NQ (2*NP)

__device__ __align__(16) float g_U[NQ*128];
__device__ float g_cmin[NQ*16];
__device__ unsigned long long g_surv[(long)NQ*8*64];
__device__ int   g_scnt[NQ*8];
__device__ int   g_knn[NQ*16];
__device__ __align__(16) float g_wu [64*128];
__device__ __align__(16) float g_w1t[64*64];
__device__ __align__(16) float g_w2t[64*128];

__device__ __forceinline__ float leaky(float v){ return fmaxf(v, 0.2f*v); }
__device__ __forceinline__ float distp(float xi,float yi,float zi,const float4 c){
    return fmaf(zi,c.z,fmaf(yi,c.y,fmaf(xi,c.x,c.w)));
}
__device__ __forceinline__ unsigned int okey(float d){
    unsigned int u = __float_as_uint(d);
    u ^= ((unsigned int)((int)u >> 31)) | 0x80000000u;
    return u;
}

// ---------------- prep: transpose weights once ----------------
__global__ void prep_kernel(const float* __restrict__ Wn, const float* __restrict__ We,
                            const float* __restrict__ W1, const float* __restrict__ W2){
    int i = blockIdx.x*blockDim.x + threadIdx.x;
    if (i < 8192){
        int c = i >> 7, o = i & 127;
        g_wu[i] = (o < 64) ? Wn[o*64 + c] : We[(o-64)*64 + c];
    } else if (i < 12288){
        int j = i - 8192; int c = j >> 6, o = j & 63;
        g_w1t[j] = W1[o*64 + c];
    } else if (i < 20480){
        int j = i - 12288; int c = j >> 7, o = j & 127;
        g_w2t[j] = W2[o*64 + c];
    }
}

// ---------- KNN pass 1: branchless chunk-mins. thread = (query, quarter of 2048) ----------
__global__ void knn_pass1(const float* __restrict__ pos){
    __shared__ float4 tile[256];
    int bx = blockIdx.x;              // 256 blocks x 256 threads
    int b  = bx >> 7;
    int r  = bx & 127;
    int quarter = r >> 5;             // [0,4)
    int n  = (r & 31)*256 + threadIdx.x;
    const float* pb = pos + b*NP*3;
    float xi = pb[n*3+0], yi = pb[n*3+1], zi = pb[n*3+2];
    long obase = ((long)(b*NP + n))*16 + quarter*4;

#pragma unroll
    for (int c4 = 0; c4 < 4; c4++){
        float mA = 3.4e38f, mB = 3.4e38f;
#pragma unroll
        for (int t2 = 0; t2 < 2; t2++){
            int jb = quarter*2048 + c4*512 + t2*256;
            int j  = jb + threadIdx.x;
            float x = pb[j*3+0], y = pb[j*3+1], z = pb[j*3+2];
            float sq = x*x; sq = fmaf(y,y,sq); sq = fmaf(z,z,sq);
            __syncthreads();
            tile[threadIdx.x] = make_float4(-2.0f*x, -2.0f*y, -2.0f*z, sq);
            __syncthreads();
#pragma unroll 8
            for (int jj = 0; jj < 256; jj += 4){
                float d0 = distp(xi,yi,zi, tile[jj+0]);
                float d1 = distp(xi,yi,zi, tile[jj+1]);
                float d2 = distp(xi,yi,zi, tile[jj+2]);
                float d3 = distp(xi,yi,zi, tile[jj+3]);
                mA = fminf(mA, fminf(d0,d1));
                mB = fminf(mB, fminf(d2,d3));
            }
        }
        g_cmin[obase + c4] = fminf(mA, mB);
    }
}

// ---------- KNN pass 2: filtered survivor scan, thread = (query, seg of 1024) ----------
__global__ void knn_pass2(const float* __restrict__ pos){
    __shared__ float4 tile[256];
    int bx  = blockIdx.x;             // 512 blocks x 256 threads
    int seg = bx & 7;
    int q   = (bx >> 3)*256 + threadIdx.x;
    int b   = q >> 13;
    int n   = q & 8191;
    const float* pb = pos + b*NP*3;
    float xi = pb[n*3+0], yi = pb[n*3+1], zi = pb[n*3+2];

    float T0 = -3.4e38f;
#pragma unroll
    for (int s = 0; s < 16; s++) T0 = fmaxf(T0, g_cmin[(long)q*16 + s]);

    unsigned long long* sv = &g_surv[((long)q*8 + seg)*64];
    int c = 0;
#pragma unroll
    for (int t = 0; t < 4; t++){
        int jb = seg*1024 + t*256;
        int j  = jb + threadIdx.x;
        float x = pb[j*3+0], y = pb[j*3+1], z = pb[j*3+2];
        float sq = x*x; sq = fmaf(y,y,sq); sq = fmaf(z,z,sq);
        __syncthreads();
        tile[threadIdx.x] = make_float4(-2.0f*x, -2.0f*y, -2.0f*z, sq);
        __syncthreads();
        for (int jj = 0; jj < 256; jj += 4){
            float d0 = distp(xi,yi,zi, tile[jj+0]);
            float d1 = distp(xi,yi,zi, tile[jj+1]);
            float d2 = distp(xi,yi,zi, tile[jj+2]);
            float d3 = distp(xi,yi,zi, tile[jj+3]);
            float mn = fminf(fminf(d0,d1), fminf(d2,d3));
            if (mn <= T0){
                float dd[4] = {d0,d1,d2,d3};
#pragma unroll
                for (int u = 0; u < 4; u++){
                    if (dd[u] <= T0 && c < 64){
                        sv[c] = ((unsigned long long)okey(dd[u]) << 32) | (unsigned int)(jb + jj + u);
                        c++;
                    }
                }
            }
        }
    }
    g_scnt[(long)q*8 + seg] = c;
}

// ---------- KNN pass 3: warp per query, smem survivor buffer, 16x warp-min ----------
__global__ void knn_pass3(const float* __restrict__ pos){
    __shared__ unsigned long long wbuf[8][512];
    int w    = threadIdx.x >> 5;
    int lane = threadIdx.x & 31;
    int q    = blockIdx.x*8 + w;       // 2048 blocks x 8 warps

    int cs = (lane < 8) ? g_scnt[(long)q*8 + lane] : 0;
    unsigned ovfm = __ballot_sync(0xffffffff, lane < 8 && cs >= 64);
    int pre = cs;
#pragma unroll
    for (int o = 1; o < 8; o <<= 1){
        int v = __shfl_up_sync(0xffffffff, pre, o);
        if (lane >= o) pre += v;
    }
    int ip[8];
#pragma unroll
    for (int s = 0; s < 8; s++) ip[s] = __shfl_sync(0xffffffff, pre, s);
    int ctot = ip[7];

    if (!ovfm){
        for (int t = lane; t < ctot; t += 32){
            int s = 0, base = 0;
#pragma unroll
            for (int k = 0; k < 7; k++){
                if (t >= ip[k]){ s = k+1; base = ip[k]; }
            }
            wbuf[w][t] = g_surv[((long)q*8 + s)*64 + (t - base)];
        }
        __syncwarp();
        for (int r = 0; r < 16; r++){
            unsigned long long mk = ~0ull; int mp = 0;
            for (int t = lane; t < ctot; t += 32){
                unsigned long long k = wbuf[w][t];
                if (k < mk){ mk = k; mp = t; }
            }
#pragma unroll
            for (int o = 16; o; o >>= 1){
                unsigned long long ok = __shfl_down_sync(0xffffffff, mk, o);
                int op = __shfl_down_sync(0xffffffff, mp, o);
                if (ok < mk){ mk = ok; mp = op; }
            }
            mp = __shfl_sync(0xffffffff, mp, 0);
            if (lane == 0){
                g_knn[(long)q*16 + r] = (int)(mk & 0xffffffffull);
                wbuf[w][mp] = ~0ull;
            }
            __syncwarp();
        }
    } else if (lane == 0){
        // exact full rescan fallback (statistically never taken)
        int b = q >> 13, n = q & 8191;
        const float* pb = pos + b*NP*3;
        float xi = pb[n*3+0], yi = pb[n*3+1], zi = pb[n*3+2];
        unsigned long long bk[16];
#pragma unroll
        for (int s = 0; s < 16; s++) bk[s] = ~0ull;
        unsigned long long worst = ~0ull; int ws = 0;
        for (int j = 0; j < NP; j++){
            float x = pb[j*3+0], y = pb[j*3+1], z = pb[j*3+2];
            float sq = x*x; sq = fmaf(y,y,sq); sq = fmaf(z,z,sq);
            float d = fmaf(zi,-2.0f*z, fmaf(yi,-2.0f*y, fmaf(xi,-2.0f*x, sq)));
            unsigned long long key = ((unsigned long long)okey(d) << 32) | (unsigned int)j;
            if (key < worst){
                bk[ws] = key;
                worst = bk[0]; ws = 0;
                for (int s = 1; s < 16; s++) if (bk[s] > worst){ worst = bk[s]; ws = s; }
            }
        }
        for (int rr = 0; rr < 16; rr++){
            unsigned long long best = ~0ull; int bj = 0;
            for (int s = 0; s < 16; s++) if (bk[s] < best){ best = bk[s]; bj = s; }
            bk[bj] = ~0ull;
            g_knn[(long)q*16 + rr] = (int)(best & 0xffffffffull);
        }
    }
}

// ---------------- U = [W_node; W_edge] * feat ----------------
__global__ void u_kernel(const float* __restrict__ feat){
    extern __shared__ float smC[];
    float* fs = smC;
    float* ws = smC + 64*128;
    int q0 = blockIdx.x*128;
    int b  = q0 >> 13;
    int n0 = q0 & 8191;
    for (int i=threadIdx.x; i<64*128; i+=256){
        int c = i>>7, nn = i&127;
        fs[i] = feat[((long)(b*64 + c))*NP + n0 + nn];
        ws[i] = g_wu[i];
    }
    __syncthreads();
    int tx = threadIdx.x & 15, ty = threadIdx.x >> 4;
    float acc[8][8];
#pragma unroll
    for (int i=0;i<8;i++)
#pragma unroll
        for (int j=0;j<8;j++) acc[i][j]=0.f;
#pragma unroll 4
    for (int c=0;c<64;c++){
        float4 a0 = *(const float4*)&fs[c*128 + ty*8];
        float4 a1 = *(const float4*)&fs[c*128 + ty*8 + 4];
        float4 w0 = *(const float4*)&ws[c*128 + tx*8];
        float4 w1 = *(const float4*)&ws[c*128 + tx*8 + 4];
        float av[8] = {a0.x,a0.y,a0.z,a0.w,a1.x,a1.y,a1.z,a1.w};
        float bv[8] = {w0.x,w0.y,w0.z,w0.w,w1.x,w1.y,w1.z,w1.w};
#pragma unroll
        for (int i=0;i<8;i++)
#pragma unroll
            for (int j=0;j<8;j++) acc[i][j] = fmaf(av[i], bv[j], acc[i][j]);
    }
#pragma unroll
    for (int i=0;i<8;i++){
        long q = q0 + ty*8 + i;
        float* r = &g_U[q*128 + tx*8];
        *(float4*)r     = make_float4(acc[i][0],acc[i][1],acc[i][2],acc[i][3]);
        *(float4*)(r+4) = make_float4(acc[i][4],acc[i][5],acc[i][6],acc[i][7]);
    }
}

// ---------------- fused gather + h1 + m1 + m2 + maxpool ----------------
__global__ void edge_main(const float* __restrict__ bn,  const float* __restrict__ be,
                          const float* __restrict__ vb1, const float* __restrict__ vb2,
                          float* __restrict__ out){
    extern __shared__ float sm[];
    float* h1T = sm;                  // [64][136], reused as h2T
    float* w1s = h1T + 64*136;
    float* w2s = w1s + 64*64;
    float* uec = w2s + 64*128;
    float* red = uec + 512;
    float* bns = red + 2048;
    float* bes = bns + 64;
    float* b1s = bes + 64;
    float* b2s = b1s + 64;
    int*   idxs = (int*)(b2s + 128);

    int q0 = blockIdx.x*8;
    int b  = q0 >> 13;
    int n0 = q0 & 8191;
    int tid = threadIdx.x;

    for (int i=tid;i<4096;i+=256) w1s[i] = g_w1t[i];
    for (int i=tid;i<8192;i+=256) w2s[i] = g_w2t[i];
    if (tid<64){ bns[tid]=bn[tid]; bes[tid]=be[tid]; b1s[tid]=vb1[tid]; }
    if (tid<128) b2s[tid]=vb2[tid];
    if (tid<128) idxs[tid] = g_knn[(long)q0*16 + tid];
    for (int i=tid;i<512;i+=256){ int p=i>>6, j=i&63; uec[i] = g_U[(long)(q0+p)*128 + 64 + j]; }
    __syncthreads();

    { // stage A
        int m  = tid >> 1;
        int jb = (tid & 1) * 32;
        int p  = m >> 4;
        int nb = idxs[m];
        const float* Ur = &g_U[(long)((b<<13) + nb)*128];
#pragma unroll
        for (int v=0; v<8; v++){
            float4 un = *(const float4*)&Ur[jb + v*4];
            float4 ue = *(const float4*)&Ur[64 + jb + v*4];
            float unv[4] = {un.x,un.y,un.z,un.w};
            float uev[4] = {ue.x,ue.y,ue.z,ue.w};
#pragma unroll
            for (int e=0;e<4;e++){
                int j = jb + v*4 + e;
                float a = leaky(unv[e] + bns[j]);
                float c = leaky(uev[e] - uec[p*64 + j] + bes[j]);
                h1T[j*136 + m] = a + c;
            }
        }
    }
    __syncthreads();

    int tx = tid & 15, ty = tid >> 4;

    { // stage B
        float acc[8][4];
#pragma unroll
        for (int i=0;i<8;i++)
#pragma unroll
            for (int o=0;o<4;o++) acc[i][o]=0.f;
#pragma unroll 4
        for (int c=0;c<64;c++){
            float4 a0 = *(const float4*)&h1T[c*136 + ty*8];
            float4 a1 = *(const float4*)&h1T[c*136 + ty*8 + 4];
            float4 wv = *(const float4*)&w1s[c*64 + tx*4];
            float av[8] = {a0.x,a0.y,a0.z,a0.w,a1.x,a1.y,a1.z,a1.w};
            float bb[4] = {wv.x,wv.y,wv.z,wv.w};
#pragma unroll
            for (int i=0;i<8;i++)
#pragma unroll
                for (int o=0;o<4;o++) acc[i][o] = fmaf(av[i], bb[o], acc[i][o]);
        }
        __syncthreads();
#pragma unroll
        for (int i=0;i<8;i++){
            int m = ty*8 + i;
#pragma unroll
            for (int o=0;o<4;o++)
                h1T[(tx*4+o)*136 + m] = leaky(acc[i][o] + b1s[tx*4+o]);
        }
    }
    __syncthreads();

    { // stage C
        float acc[8][8];
#pragma unroll
        for (int i=0;i<8;i++)
#pragma unroll
            for (int o=0;o<8;o++) acc[i][o]=0.f;
#pragma unroll 4
        for (int c=0;c<64;c++){
            float4 a0 = *(const float4*)&h1T[c*136 + ty*8];
            float4 a1 = *(const float4*)&h1T[c*136 + ty*8 + 4];
            float4 w0 = *(const float4*)&w2s[c*128 + tx*8];
            float4 w1 = *(const float4*)&w2s[c*128 + tx*8 + 4];
            float av[8] = {a0.x,a0.y,a0.z,a0.w,a1.x,a1.y,a1.z,a1.w};
            float bb[8] = {w0.x,w0.y,w0.z,w0.w,w1.x,w1.y,w1.z,w1.w};
#pragma unroll
            for (int i=0;i<8;i++)
#pragma unroll
                for (int o=0;o<8;o++) acc[i][o] = fmaf(av[i], bb[o], acc[i][o]);
        }
#pragma unroll
        for (int o=0;o<8;o++){
            float bias = b2s[tx*8+o];
            float pm = -3.4e38f;
#pragma unroll
            for (int i=0;i<8;i++)
                pm = fmaxf(pm, leaky(acc[i][o] + bias));
            red[ty*128 + tx*8 + o] = pm;
        }
    }
    __syncthreads();

    for (int e=tid; e<1024; e+=256){
        int o = e & 127;
        int p = e >> 7;
        float v = fmaxf(red[(2*p)*128 + o], red[(2*p+1)*128 + o]);
        out[((long)(b*128 + o))*NP + n0 + p] = v;
    }
}

extern "C" void kernel_launch(void* const* d_in, const int* in_sizes, int n_in,
                              void* d_out, int out_size){
    const float* feat = (const float*)d_in[0];
    const float* pos  = (const float*)d_in[1];
    const float* Wn   = (const float*)d_in[2];
    const float* bn   = (const float*)d_in[3];
    const float* We   = (const float*)d_in[4];
    const float* be   = (const float*)d_in[5];
    const float* W1   = (const float*)d_in[6];
    const float* b1   = (const float*)d_in[7];
    const float* W2   = (const float*)d_in[8];
    const float* b2   = (const float*)d_in[9];
    float* out = (float*)d_out;

    cudaFuncSetAttribute(u_kernel,  cudaFuncAttributeMaxDynamicSharedMemorySize, 65536);
    cudaFuncSetAttribute(edge_main, cudaFuncAttributeMaxDynamicSharedMemorySize, 98304);

    prep_kernel<<<80,256>>>(Wn, We, W1, W2);
    knn_pass1<<<256,256>>>(pos);
    knn_pass2<<<512,256>>>(pos);
    knn_pass3<<<2048,256>>>(pos);
    u_kernel<<<128,256,65536>>>(feat);
    edge_main<<<2048,256,96000>>>(bn, be, b1, b2, out);
}

// round 11
// speedup vs baseline: 3.4501x; 1.0062x over previous
#include <cuda_runtime.h>

#define NP 8192
#define NQ (2*NP)

__device__ __align__(16) float g_U[NQ*128];
__device__ float g_cmin[NQ*16];
__device__ unsigned long long g_surv[(long)NQ*8*64];
__device__ int   g_scnt[NQ*8];
__device__ int   g_knn[NQ*16];
__device__ __align__(16) float g_wu [64*128];
__device__ __align__(16) float g_w1t[64*64];
__device__ __align__(16) float g_w2t[64*128];

__device__ __forceinline__ float leaky(float v){ return fmaxf(v, 0.2f*v); }
__device__ __forceinline__ float distp(float xi,float yi,float zi,const float4 c){
    return fmaf(zi,c.z,fmaf(yi,c.y,fmaf(xi,c.x,c.w)));
}
__device__ __forceinline__ unsigned int okey(float d){
    unsigned int u = __float_as_uint(d);
    u ^= ((unsigned int)((int)u >> 31)) | 0x80000000u;
    return u;
}
__device__ __forceinline__ unsigned long long umin64(unsigned long long a, unsigned long long b){
    return a < b ? a : b;
}
__device__ __forceinline__ void fma2(unsigned long long &acc, unsigned long long a, unsigned long long b){
    asm("fma.rn.f32x2 %0, %1, %2, %0;" : "+l"(acc) : "l"(a), "l"(b));
}
__device__ __forceinline__ unsigned long long splat2(float v){
    unsigned long long r;
    asm("mov.b64 %0, {%1, %1};" : "=l"(r) : "f"(v));
    return r;
}
__device__ __forceinline__ void unpack2(unsigned long long v, float &lo, float &hi){
    asm("mov.b64 {%0, %1}, %2;" : "=f"(lo), "=f"(hi) : "l"(v));
}

// ---------------- prep: transpose weights once ----------------
__global__ void prep_kernel(const float* __restrict__ Wn, const float* __restrict__ We,
                            const float* __restrict__ W1, const float* __restrict__ W2){
    int i = blockIdx.x*blockDim.x + threadIdx.x;
    if (i < 8192){
        int c = i >> 7, o = i & 127;
        g_wu[i] = (o < 64) ? Wn[o*64 + c] : We[(o-64)*64 + c];
    } else if (i < 12288){
        int j = i - 8192; int c = j >> 6, o = j & 63;
        g_w1t[j] = W1[o*64 + c];
    } else if (i < 20480){
        int j = i - 12288; int c = j >> 7, o = j & 127;
        g_w2t[j] = W2[o*64 + c];
    }
}

// ---------- KNN pass 1: branchless chunk-mins. thread = (query, quarter of 2048) ----------
__global__ void knn_pass1(const float* __restrict__ pos){
    __shared__ float4 tile[256];
    int bx = blockIdx.x;              // 256 blocks x 256 threads
    int b  = bx >> 7;
    int r  = bx & 127;
    int quarter = r >> 5;
    int n  = (r & 31)*256 + threadIdx.x;
    const float* pb = pos + b*NP*3;
    float xi = pb[n*3+0], yi = pb[n*3+1], zi = pb[n*3+2];
    long obase = ((long)(b*NP + n))*16 + quarter*4;

#pragma unroll
    for (int c4 = 0; c4 < 4; c4++){
        float mA = 3.4e38f, mB = 3.4e38f;
#pragma unroll
        for (int t2 = 0; t2 < 2; t2++){
            int jb = quarter*2048 + c4*512 + t2*256;
            int j  = jb + threadIdx.x;
            float x = pb[j*3+0], y = pb[j*3+1], z = pb[j*3+2];
            float sq = x*x; sq = fmaf(y,y,sq); sq = fmaf(z,z,sq);
            __syncthreads();
            tile[threadIdx.x] = make_float4(-2.0f*x, -2.0f*y, -2.0f*z, sq);
            __syncthreads();
#pragma unroll 8
            for (int jj = 0; jj < 256; jj += 4){
                float d0 = distp(xi,yi,zi, tile[jj+0]);
                float d1 = distp(xi,yi,zi, tile[jj+1]);
                float d2 = distp(xi,yi,zi, tile[jj+2]);
                float d3 = distp(xi,yi,zi, tile[jj+3]);
                mA = fminf(mA, fminf(d0,d1));
                mB = fminf(mB, fminf(d2,d3));
            }
        }
        g_cmin[obase + c4] = fminf(mA, mB);
    }
}

// ---------- KNN pass 2: filtered survivor scan, thread = (query, seg of 1024) ----------
__global__ void knn_pass2(const float* __restrict__ pos){
    __shared__ float4 tile[256];
    int bx  = blockIdx.x;             // 512 blocks x 256 threads
    int seg = bx & 7;
    int q   = (bx >> 3)*256 + threadIdx.x;
    int b   = q >> 13;
    int n   = q & 8191;
    const float* pb = pos + b*NP*3;
    float xi = pb[n*3+0], yi = pb[n*3+1], zi = pb[n*3+2];

    float T0 = -3.4e38f;
#pragma unroll
    for (int s = 0; s < 16; s++) T0 = fmaxf(T0, g_cmin[(long)q*16 + s]);

    unsigned long long* sv = &g_surv[((long)q*8 + seg)*64];
    int c = 0;
#pragma unroll
    for (int t = 0; t < 4; t++){
        int jb = seg*1024 + t*256;
        int j  = jb + threadIdx.x;
        float x = pb[j*3+0], y = pb[j*3+1], z = pb[j*3+2];
        float sq = x*x; sq = fmaf(y,y,sq); sq = fmaf(z,z,sq);
        __syncthreads();
        tile[threadIdx.x] = make_float4(-2.0f*x, -2.0f*y, -2.0f*z, sq);
        __syncthreads();
        for (int jj = 0; jj < 256; jj += 4){
            float d0 = distp(xi,yi,zi, tile[jj+0]);
            float d1 = distp(xi,yi,zi, tile[jj+1]);
            float d2 = distp(xi,yi,zi, tile[jj+2]);
            float d3 = distp(xi,yi,zi, tile[jj+3]);
            float mn = fminf(fminf(d0,d1), fminf(d2,d3));
            if (mn <= T0){
                float dd[4] = {d0,d1,d2,d3};
#pragma unroll
                for (int u = 0; u < 4; u++){
                    if (dd[u] <= T0 && c < 64){
                        sv[c] = ((unsigned long long)okey(dd[u]) << 32) | (unsigned int)(jb + jj + u);
                        c++;
                    }
                }
            }
        }
    }
    g_scnt[(long)q*8 + seg] = c;
}

// ---------- KNN pass 3: warp/query, 8 register keys/lane (cap 256), 16 warp-min rounds ----------
__global__ void knn_pass3(const float* __restrict__ pos){
    int w    = threadIdx.x >> 5;
    int lane = threadIdx.x & 31;
    int q    = blockIdx.x*8 + w;       // 2048 blocks x 8 warps

    int cs = (lane < 8) ? g_scnt[(long)q*8 + lane] : 0;
    unsigned ovfm = __ballot_sync(0xffffffff, lane < 8 && cs >= 64);
    int pre = cs;
#pragma unroll
    for (int o = 1; o < 8; o <<= 1){
        int v = __shfl_up_sync(0xffffffff, pre, o);
        if (lane >= o) pre += v;
    }
    int ip[8];
#pragma unroll
    for (int s = 0; s < 8; s++) ip[s] = __shfl_sync(0xffffffff, pre, s);
    int ctot = ip[7];

    if (!ovfm && ctot <= 256){
        unsigned long long k[8];
#pragma unroll
        for (int u = 0; u < 8; u++){
            int t = lane + u*32;
            unsigned long long key = ~0ull;
            if (t < ctot){
                int s = 0, base = 0;
#pragma unroll
                for (int kk = 0; kk < 7; kk++){
                    if (t >= ip[kk]){ s = kk+1; base = ip[kk]; }
                }
                key = g_surv[((long)q*8 + s)*64 + (t - base)];
            }
            k[u] = key;
        }
        for (int r = 0; r < 16; r++){
            unsigned long long best = k[0];
#pragma unroll
            for (int u = 1; u < 8; u++) best = umin64(best, k[u]);
            unsigned long long rb = best;
#pragma unroll
            for (int o = 16; o; o >>= 1)
                rb = umin64(rb, __shfl_down_sync(0xffffffff, rb, o));
            rb = __shfl_sync(0xffffffff, rb, 0);
            if (lane == 0) g_knn[(long)q*16 + r] = (int)(rb & 0xffffffffull);
            if (best == rb){
#pragma unroll
                for (int u = 0; u < 8; u++) if (k[u] == rb) k[u] = ~0ull;
            }
        }
    } else if (lane == 0){
        // exact full rescan fallback (probability ~0 with cap 256)
        int b = q >> 13, n = q & 8191;
        const float* pb = pos + b*NP*3;
        float xi = pb[n*3+0], yi = pb[n*3+1], zi = pb[n*3+2];
        unsigned long long bk[16];
#pragma unroll
        for (int s = 0; s < 16; s++) bk[s] = ~0ull;
        unsigned long long worst = ~0ull; int ws = 0;
        for (int j = 0; j < NP; j++){
            float x = pb[j*3+0], y = pb[j*3+1], z = pb[j*3+2];
            float sq = x*x; sq = fmaf(y,y,sq); sq = fmaf(z,z,sq);
            float d = fmaf(zi,-2.0f*z, fmaf(yi,-2.0f*y, fmaf(xi,-2.0f*x, sq)));
            unsigned long long key = ((unsigned long long)okey(d) << 32) | (unsigned int)j;
            if (key < worst){
                bk[ws] = key;
                worst = bk[0]; ws = 0;
                for (int s = 1; s < 16; s++) if (bk[s] > worst){ worst = bk[s]; ws = s; }
            }
        }
        for (int rr = 0; rr < 16; rr++){
            unsigned long long best = ~0ull; int bj = 0;
            for (int s = 0; s < 16; s++) if (bk[s] < best){ best = bk[s]; bj = s; }
            bk[bj] = ~0ull;
            g_knn[(long)q*16 + rr] = (int)(best & 0xffffffffull);
        }
    }
}

// ---------------- U = [W_node; W_edge] * feat ----------------
__global__ void u_kernel(const float* __restrict__ feat){
    extern __shared__ float smC[];
    float* fs = smC;
    float* ws = smC + 64*128;
    int q0 = blockIdx.x*128;
    int b  = q0 >> 13;
    int n0 = q0 & 8191;
    for (int i=threadIdx.x; i<64*128; i+=256){
        int c = i>>7, nn = i&127;
        fs[i] = feat[((long)(b*64 + c))*NP + n0 + nn];
        ws[i] = g_wu[i];
    }
    __syncthreads();
    int tx = threadIdx.x & 15, ty = threadIdx.x >> 4;
    float acc[8][8];
#pragma unroll
    for (int i=0;i<8;i++)
#pragma unroll
        for (int j=0;j<8;j++) acc[i][j]=0.f;
#pragma unroll 4
    for (int c=0;c<64;c++){
        float4 a0 = *(const float4*)&fs[c*128 + ty*8];
        float4 a1 = *(const float4*)&fs[c*128 + ty*8 + 4];
        float4 w0 = *(const float4*)&ws[c*128 + tx*8];
        float4 w1 = *(const float4*)&ws[c*128 + tx*8 + 4];
        float av[8] = {a0.x,a0.y,a0.z,a0.w,a1.x,a1.y,a1.z,a1.w};
        float bv[8] = {w0.x,w0.y,w0.z,w0.w,w1.x,w1.y,w1.z,w1.w};
#pragma unroll
        for (int i=0;i<8;i++)
#pragma unroll
            for (int j=0;j<8;j++) acc[i][j] = fmaf(av[i], bv[j], acc[i][j]);
    }
#pragma unroll
    for (int i=0;i<8;i++){
        long q = q0 + ty*8 + i;
        float* r = &g_U[q*128 + tx*8];
        *(float4*)r     = make_float4(acc[i][0],acc[i][1],acc[i][2],acc[i][3]);
        *(float4*)(r+4) = make_float4(acc[i][4],acc[i][5],acc[i][6],acc[i][7]);
    }
}

// -------- fused gather + h1 + m1 + m2 + maxpool (f32x2, register-capped) --------
__global__ void __launch_bounds__(256, 2)
edge_main(const float* __restrict__ bn,  const float* __restrict__ be,
          const float* __restrict__ vb1, const float* __restrict__ vb2,
          float* __restrict__ out){
    extern __shared__ float sm[];
    float* h1T = sm;                  // [64][136], reused as h2T
    float* w1s = h1T + 64*136;
    float* w2s = w1s + 64*64;
    float* uec = w2s + 64*128;
    float* red = uec + 512;
    float* bns = red + 2048;
    float* bes = bns + 64;
    float* b1s = bes + 64;
    float* b2s = b1s + 64;
    int*   idxs = (int*)(b2s + 128);

    int q0 = blockIdx.x*8;
    int b  = q0 >> 13;
    int n0 = q0 & 8191;
    int tid = threadIdx.x;

    for (int i=tid;i<4096;i+=256) w1s[i] = g_w1t[i];
    for (int i=tid;i<8192;i+=256) w2s[i] = g_w2t[i];
    if (tid<64){ bns[tid]=bn[tid]; bes[tid]=be[tid]; b1s[tid]=vb1[tid]; }
    if (tid<128) b2s[tid]=vb2[tid];
    if (tid<128) idxs[tid] = g_knn[(long)q0*16 + tid];
    for (int i=tid;i<512;i+=256){ int p=i>>6, j=i&63; uec[i] = g_U[(long)(q0+p)*128 + 64 + j]; }
    __syncthreads();

    { // stage A: gather + layer1 -> h1T[j][m]
        int m  = tid >> 1;
        int jb = (tid & 1) * 32;
        int p  = m >> 4;
        int nb = idxs[m];
        const float* Ur = &g_U[(long)((b<<13) + nb)*128];
#pragma unroll
        for (int v=0; v<8; v++){
            float4 un = *(const float4*)&Ur[jb + v*4];
            float4 ue = *(const float4*)&Ur[64 + jb + v*4];
            float unv[4] = {un.x,un.y,un.z,un.w};
            float uev[4] = {ue.x,ue.y,ue.z,ue.w};
#pragma unroll
            for (int e=0;e<4;e++){
                int j = jb + v*4 + e;
                float a = leaky(unv[e] + bns[j]);
                float c = leaky(uev[e] - uec[p*64 + j] + bes[j]);
                h1T[j*136 + m] = a + c;
            }
        }
    }
    __syncthreads();

    int tx = tid & 15, ty = tid >> 4;

    { // stage B: M=128 N=64 K=64, f32x2 packed along m
        unsigned long long acc2[4][4];
#pragma unroll
        for (int i=0;i<4;i++)
#pragma unroll
            for (int o=0;o<4;o++) acc2[i][o]=0ull;
#pragma unroll 4
        for (int c=0;c<64;c++){
            ulonglong2 a01 = *(const ulonglong2*)&h1T[c*136 + ty*8];
            ulonglong2 a23 = *(const ulonglong2*)&h1T[c*136 + ty*8 + 4];
            float4 wv = *(const float4*)&w1s[c*64 + tx*4];
            unsigned long long bs0 = splat2(wv.x), bs1 = splat2(wv.y),
                               bs2 = splat2(wv.z), bs3 = splat2(wv.w);
            unsigned long long av[4] = {a01.x, a01.y, a23.x, a23.y};
#pragma unroll
            for (int i=0;i<4;i++){
                fma2(acc2[i][0], av[i], bs0);
                fma2(acc2[i][1], av[i], bs1);
                fma2(acc2[i][2], av[i], bs2);
                fma2(acc2[i][3], av[i], bs3);
            }
        }
        __syncthreads();
#pragma unroll
        for (int i=0;i<4;i++){
            int m = ty*8 + i*2;
#pragma unroll
            for (int o=0;o<4;o++){
                float lo, hi; unpack2(acc2[i][o], lo, hi);
                float bias = b1s[tx*4+o];
                h1T[(tx*4+o)*136 + m]     = leaky(lo + bias);
                h1T[(tx*4+o)*136 + m + 1] = leaky(hi + bias);
            }
        }
    }
    __syncthreads();

    { // stage C: M=128 N=128 K=64, f32x2, two o-halves of 4
#pragma unroll
        for (int h = 0; h < 2; h++){
            unsigned long long acc2[4][4];
#pragma unroll
            for (int i=0;i<4;i++)
#pragma unroll
                for (int o=0;o<4;o++) acc2[i][o]=0ull;
#pragma unroll 4
            for (int c=0;c<64;c++){
                ulonglong2 a01 = *(const ulonglong2*)&h1T[c*136 + ty*8];
                ulonglong2 a23 = *(const ulonglong2*)&h1T[c*136 + ty*8 + 4];
                float4 wv = *(const float4*)&w2s[c*128 + tx*8 + h*4];
                unsigned long long bs0 = splat2(wv.x), bs1 = splat2(wv.y),
                                   bs2 = splat2(wv.z), bs3 = splat2(wv.w);
                unsigned long long av[4] = {a01.x, a01.y, a23.x, a23.y};
#pragma unroll
                for (int i=0;i<4;i++){
                    fma2(acc2[i][0], av[i], bs0);
                    fma2(acc2[i][1], av[i], bs1);
                    fma2(acc2[i][2], av[i], bs2);
                    fma2(acc2[i][3], av[i], bs3);
                }
            }
#pragma unroll
            for (int o=0;o<4;o++){
                float bias = b2s[tx*8 + h*4 + o];
                float pm = -3.4e38f;
#pragma unroll
                for (int i=0;i<4;i++){
                    float lo, hi; unpack2(acc2[i][o], lo, hi);
                    pm = fmaxf(pm, leaky(lo + bias));
                    pm = fmaxf(pm, leaky(hi + bias));
                }
                red[ty*128 + tx*8 + h*4 + o] = pm;
            }
        }
    }
    __syncthreads();

    for (int e=tid; e<1024; e+=256){
        int o = e & 127;
        int p = e >> 7;
        float v = fmaxf(red[(2*p)*128 + o], red[(2*p+1)*128 + o]);
        out[((long)(b*128 + o))*NP + n0 + p] = v;
    }
}

extern "C" void kernel_launch(void* const* d_in, const int* in_sizes, int n_in,
                              void* d_out, int out_size){
    const float* feat = (const float*)d_in[0];
    const float* pos  = (const float*)d_in[1];
    const float* Wn   = (const float*)d_in[2];
    const float* bn   = (const float*)d_in[3];
    const float* We   = (const float*)d_in[4];
    const float* be   = (const float*)d_in[5];
    const float* W1   = (const float*)d_in[6];
    const float* b1   = (const float*)d_in[7];
    const float* W2   = (const float*)d_in[8];
    const float* b2   = (const float*)d_in[9];
    float* out = (float*)d_out;

    cudaFuncSetAttribute(u_kernel,  cudaFuncAttributeMaxDynamicSharedMemorySize, 65536);
    cudaFuncSetAttribute(edge_main, cudaFuncAttributeMaxDynamicSharedMemorySize, 98304);

    prep_kernel<<<80,256>>>(Wn, We, W1, W2);
    knn_pass1<<<256,256>>>(pos);
    knn_pass2<<<512,256>>>(pos);
    knn_pass3<<<2048,256>>>(pos);
    u_kernel<<<128,256,65536>>>(feat);
    edge_main<<<2048,256,96000>>>(bn, be, b1, b2, out);
}

// round 12
// speedup vs baseline: 3.5632x; 1.0328x over previous
#include <cuda_runtime.h>

#define NP 8192
#define NQ (2*NP)

__device__ __align__(16) float g_U[NQ*128];
__device__ float g_cmin[NQ*16];
__device__ unsigned long long g_surv[(long)NQ*16*32];
__device__ int   g_scnt[NQ*16];
__device__ int   g_knn[NQ*16];
__device__ __align__(16) float g_wu [64*128];
__device__ __align__(16) float g_w1t[64*64];
__device__ __align__(16) float g_w2t[64*128];

__device__ __forceinline__ float leaky(float v){ return fmaxf(v, 0.2f*v); }
__device__ __forceinline__ float distp(float xi,float yi,float zi,const float4 c){
    return fmaf(zi,c.z,fmaf(yi,c.y,fmaf(xi,c.x,c.w)));
}
__device__ __forceinline__ unsigned int okey(float d){
    unsigned int u = __float_as_uint(d);
    u ^= ((unsigned int)((int)u >> 31)) | 0x80000000u;
    return u;
}
__device__ __forceinline__ unsigned long long umin64(unsigned long long a, unsigned long long b){
    return a < b ? a : b;
}
__device__ __forceinline__ void fma2(unsigned long long &acc, unsigned long long a, unsigned long long b){
    asm("fma.rn.f32x2 %0, %1, %2, %0;" : "+l"(acc) : "l"(a), "l"(b));
}
__device__ __forceinline__ unsigned long long splat2(float v){
    unsigned long long r;
    asm("mov.b64 %0, {%1, %1};" : "=l"(r) : "f"(v));
    return r;
}
__device__ __forceinline__ void unpack2(unsigned long long v, float &lo, float &hi){
    asm("mov.b64 {%0, %1}, %2;" : "=f"(lo), "=f"(hi) : "l"(v));
}

// ---------------- prep: transpose weights once ----------------
__global__ void prep_kernel(const float* __restrict__ Wn, const float* __restrict__ We,
                            const float* __restrict__ W1, const float* __restrict__ W2){
    int i = blockIdx.x*blockDim.x + threadIdx.x;
    if (i < 8192){
        int c = i >> 7, o = i & 127;
        g_wu[i] = (o < 64) ? Wn[o*64 + c] : We[(o-64)*64 + c];
    } else if (i < 12288){
        int j = i - 8192; int c = j >> 6, o = j & 63;
        g_w1t[j] = W1[o*64 + c];
    } else if (i < 20480){
        int j = i - 12288; int c = j >> 7, o = j & 127;
        g_w2t[j] = W2[o*64 + c];
    }
}

// ---------- KNN pass 1: branchless chunk-mins. thread = (query, eighth of 1024) ----------
// chunk structure unchanged: 16 chunks of 512 per query; each thread computes 2 chunk-mins.
__global__ void knn_pass1(const float* __restrict__ pos){
    __shared__ float4 tile[256];
    int bx = blockIdx.x;              // 512 blocks x 256 threads
    int b  = bx >> 8;
    int r  = bx & 255;
    int eighth = r >> 5;              // [0,8)
    int n  = (r & 31)*256 + threadIdx.x;
    const float* pb = pos + b*NP*3;
    float xi = pb[n*3+0], yi = pb[n*3+1], zi = pb[n*3+2];
    long obase = ((long)(b*NP + n))*16 + eighth*2;

#pragma unroll
    for (int c2 = 0; c2 < 2; c2++){
        float mA = 3.4e38f, mB = 3.4e38f;
#pragma unroll
        for (int t2 = 0; t2 < 2; t2++){
            int jb = eighth*1024 + c2*512 + t2*256;
            int j  = jb + threadIdx.x;
            float x = pb[j*3+0], y = pb[j*3+1], z = pb[j*3+2];
            float sq = x*x; sq = fmaf(y,y,sq); sq = fmaf(z,z,sq);
            __syncthreads();
            tile[threadIdx.x] = make_float4(-2.0f*x, -2.0f*y, -2.0f*z, sq);
            __syncthreads();
#pragma unroll 8
            for (int jj = 0; jj < 256; jj += 4){
                float d0 = distp(xi,yi,zi, tile[jj+0]);
                float d1 = distp(xi,yi,zi, tile[jj+1]);
                float d2 = distp(xi,yi,zi, tile[jj+2]);
                float d3 = distp(xi,yi,zi, tile[jj+3]);
                mA = fminf(mA, fminf(d0,d1));
                mB = fminf(mB, fminf(d2,d3));
            }
        }
        g_cmin[obase + c2] = fminf(mA, mB);
    }
}

// ---------- KNN pass 2: filtered survivor scan, thread = (query, seg of 512) ----------
__global__ void knn_pass2(const float* __restrict__ pos){
    __shared__ float4 tile[256];
    int bx  = blockIdx.x;             // 1024 blocks x 256 threads
    int seg = bx & 15;
    int q   = (bx >> 4)*256 + threadIdx.x;
    int b   = q >> 13;
    int n   = q & 8191;
    const float* pb = pos + b*NP*3;
    float xi = pb[n*3+0], yi = pb[n*3+1], zi = pb[n*3+2];

    float T0 = -3.4e38f;
#pragma unroll
    for (int s = 0; s < 16; s++) T0 = fmaxf(T0, g_cmin[(long)q*16 + s]);

    unsigned long long* sv = &g_surv[((long)q*16 + seg)*32];
    int c = 0;
#pragma unroll
    for (int t = 0; t < 2; t++){
        int jb = seg*512 + t*256;
        int j  = jb + threadIdx.x;
        float x = pb[j*3+0], y = pb[j*3+1], z = pb[j*3+2];
        float sq = x*x; sq = fmaf(y,y,sq); sq = fmaf(z,z,sq);
        __syncthreads();
        tile[threadIdx.x] = make_float4(-2.0f*x, -2.0f*y, -2.0f*z, sq);
        __syncthreads();
        for (int jj = 0; jj < 256; jj += 4){
            float d0 = distp(xi,yi,zi, tile[jj+0]);
            float d1 = distp(xi,yi,zi, tile[jj+1]);
            float d2 = distp(xi,yi,zi, tile[jj+2]);
            float d3 = distp(xi,yi,zi, tile[jj+3]);
            float mn = fminf(fminf(d0,d1), fminf(d2,d3));
            if (mn <= T0){
                float dd[4] = {d0,d1,d2,d3};
#pragma unroll
                for (int u = 0; u < 4; u++){
                    if (dd[u] <= T0 && c < 32){
                        sv[c] = ((unsigned long long)okey(dd[u]) << 32) | (unsigned int)(jb + jj + u);
                        c++;
                    }
                }
            }
        }
    }
    g_scnt[(long)q*16 + seg] = c;
}

// ---------- KNN pass 3: warp/query, register keys, fast path for ctot<=128 ----------
__global__ void knn_pass3(const float* __restrict__ pos){
    int w    = threadIdx.x >> 5;
    int lane = threadIdx.x & 31;
    int q    = blockIdx.x*8 + w;       // 2048 blocks x 8 warps

    int cs = (lane < 16) ? g_scnt[(long)q*16 + lane] : 0;
    unsigned ovfm = __ballot_sync(0xffffffff, lane < 16 && cs >= 32);
    int pre = cs;
#pragma unroll
    for (int o = 1; o < 16; o <<= 1){
        int v = __shfl_up_sync(0xffffffff, pre, o);
        if (lane >= o) pre += v;
    }
    int ip[16];
#pragma unroll
    for (int s = 0; s < 16; s++) ip[s] = __shfl_sync(0xffffffff, pre, s);
    int ctot = ip[15];

    if (!ovfm && ctot <= 256){
        unsigned long long k[8];
#pragma unroll
        for (int u = 0; u < 8; u++){
            int t = lane + u*32;
            unsigned long long key = ~0ull;
            if (t < ctot){
                int s = 0, base = 0;
#pragma unroll
                for (int kk = 0; kk < 15; kk++){
                    if (t >= ip[kk]){ s = kk+1; base = ip[kk]; }
                }
                key = g_surv[((long)q*16 + s)*32 + (t - base)];
            }
            k[u] = key;
        }
        if (ctot <= 128){
            // fast path: only k[0..3] can hold real keys
            for (int r = 0; r < 16; r++){
                unsigned long long best = umin64(umin64(k[0],k[1]), umin64(k[2],k[3]));
                unsigned long long rb = best;
#pragma unroll
                for (int o = 16; o; o >>= 1)
                    rb = umin64(rb, __shfl_down_sync(0xffffffff, rb, o));
                rb = __shfl_sync(0xffffffff, rb, 0);
                if (lane == 0) g_knn[(long)q*16 + r] = (int)(rb & 0xffffffffull);
                if (best == rb){
#pragma unroll
                    for (int u = 0; u < 4; u++) if (k[u] == rb) k[u] = ~0ull;
                }
            }
        } else {
            for (int r = 0; r < 16; r++){
                unsigned long long best = k[0];
#pragma unroll
                for (int u = 1; u < 8; u++) best = umin64(best, k[u]);
                unsigned long long rb = best;
#pragma unroll
                for (int o = 16; o; o >>= 1)
                    rb = umin64(rb, __shfl_down_sync(0xffffffff, rb, o));
                rb = __shfl_sync(0xffffffff, rb, 0);
                if (lane == 0) g_knn[(long)q*16 + r] = (int)(rb & 0xffffffffull);
                if (best == rb){
#pragma unroll
                    for (int u = 0; u < 8; u++) if (k[u] == rb) k[u] = ~0ull;
                }
            }
        }
    } else if (lane == 0){
        // exact full rescan fallback (probability ~0)
        int b = q >> 13, n = q & 8191;
        const float* pb = pos + b*NP*3;
        float xi = pb[n*3+0], yi = pb[n*3+1], zi = pb[n*3+2];
        unsigned long long bk[16];
#pragma unroll
        for (int s = 0; s < 16; s++) bk[s] = ~0ull;
        unsigned long long worst = ~0ull; int ws = 0;
        for (int j = 0; j < NP; j++){
            float x = pb[j*3+0], y = pb[j*3+1], z = pb[j*3+2];
            float sq = x*x; sq = fmaf(y,y,sq); sq = fmaf(z,z,sq);
            float d = fmaf(zi,-2.0f*z, fmaf(yi,-2.0f*y, fmaf(xi,-2.0f*x, sq)));
            unsigned long long key = ((unsigned long long)okey(d) << 32) | (unsigned int)j;
            if (key < worst){
                bk[ws] = key;
                worst = bk[0]; ws = 0;
                for (int s = 1; s < 16; s++) if (bk[s] > worst){ worst = bk[s]; ws = s; }
            }
        }
        for (int rr = 0; rr < 16; rr++){
            unsigned long long best = ~0ull; int bj = 0;
            for (int s = 0; s < 16; s++) if (bk[s] < best){ best = bk[s]; bj = s; }
            bk[bj] = ~0ull;
            g_knn[(long)q*16 + rr] = (int)(best & 0xffffffffull);
        }
    }
}

// ---------------- U = [W_node; W_edge] * feat ----------------
__global__ void u_kernel(const float* __restrict__ feat){
    extern __shared__ float smC[];
    float* fs = smC;
    float* ws = smC + 64*128;
    int q0 = blockIdx.x*128;
    int b  = q0 >> 13;
    int n0 = q0 & 8191;
    for (int i=threadIdx.x; i<64*128; i+=256){
        int c = i>>7, nn = i&127;
        fs[i] = feat[((long)(b*64 + c))*NP + n0 + nn];
        ws[i] = g_wu[i];
    }
    __syncthreads();
    int tx = threadIdx.x & 15, ty = threadIdx.x >> 4;
    float acc[8][8];
#pragma unroll
    for (int i=0;i<8;i++)
#pragma unroll
        for (int j=0;j<8;j++) acc[i][j]=0.f;
#pragma unroll 4
    for (int c=0;c<64;c++){
        float4 a0 = *(const float4*)&fs[c*128 + ty*8];
        float4 a1 = *(const float4*)&fs[c*128 + ty*8 + 4];
        float4 w0 = *(const float4*)&ws[c*128 + tx*8];
        float4 w1 = *(const float4*)&ws[c*128 + tx*8 + 4];
        float av[8] = {a0.x,a0.y,a0.z,a0.w,a1.x,a1.y,a1.z,a1.w};
        float bv[8] = {w0.x,w0.y,w0.z,w0.w,w1.x,w1.y,w1.z,w1.w};
#pragma unroll
        for (int i=0;i<8;i++)
#pragma unroll
            for (int j=0;j<8;j++) acc[i][j] = fmaf(av[i], bv[j], acc[i][j]);
    }
#pragma unroll
    for (int i=0;i<8;i++){
        long q = q0 + ty*8 + i;
        float* r = &g_U[q*128 + tx*8];
        *(float4*)r     = make_float4(acc[i][0],acc[i][1],acc[i][2],acc[i][3]);
        *(float4*)(r+4) = make_float4(acc[i][4],acc[i][5],acc[i][6],acc[i][7]);
    }
}

// -------- fused gather + h1 + m1 + m2 + maxpool (f32x2, register-capped) --------
__global__ void __launch_bounds__(256, 2)
edge_main(const float* __restrict__ bn,  const float* __restrict__ be,
          const float* __restrict__ vb1, const float* __restrict__ vb2,
          float* __restrict__ out){
    extern __shared__ float sm[];
    float* h1T = sm;                  // [64][136], reused as h2T
    float* w1s = h1T + 64*136;
    float* w2s = w1s + 64*64;
    float* uec = w2s + 64*128;
    float* red = uec + 512;
    float* bns = red + 2048;
    float* bes = bns + 64;
    float* b1s = bes + 64;
    float* b2s = b1s + 64;
    int*   idxs = (int*)(b2s + 128);

    int q0 = blockIdx.x*8;
    int b  = q0 >> 13;
    int n0 = q0 & 8191;
    int tid = threadIdx.x;

    for (int i=tid;i<4096;i+=256) w1s[i] = g_w1t[i];
    for (int i=tid;i<8192;i+=256) w2s[i] = g_w2t[i];
    if (tid<64){ bns[tid]=bn[tid]; bes[tid]=be[tid]; b1s[tid]=vb1[tid]; }
    if (tid<128) b2s[tid]=vb2[tid];
    if (tid<128) idxs[tid] = g_knn[(long)q0*16 + tid];
    for (int i=tid;i<512;i+=256){ int p=i>>6, j=i&63; uec[i] = g_U[(long)(q0+p)*128 + 64 + j]; }
    __syncthreads();

    { // stage A: gather + layer1 -> h1T[j][m]
        int m  = tid >> 1;
        int jb = (tid & 1) * 32;
        int p  = m >> 4;
        int nb = idxs[m];
        const float* Ur = &g_U[(long)((b<<13) + nb)*128];
#pragma unroll
        for (int v=0; v<8; v++){
            float4 un = *(const float4*)&Ur[jb + v*4];
            float4 ue = *(const float4*)&Ur[64 + jb + v*4];
            float unv[4] = {un.x,un.y,un.z,un.w};
            float uev[4] = {ue.x,ue.y,ue.z,ue.w};
#pragma unroll
            for (int e=0;e<4;e++){
                int j = jb + v*4 + e;
                float a = leaky(unv[e] + bns[j]);
                float c = leaky(uev[e] - uec[p*64 + j] + bes[j]);
                h1T[j*136 + m] = a + c;
            }
        }
    }
    __syncthreads();

    int tx = tid & 15, ty = tid >> 4;

    { // stage B: M=128 N=64 K=64, f32x2 packed along m
        unsigned long long acc2[4][4];
#pragma unroll
        for (int i=0;i<4;i++)
#pragma unroll
            for (int o=0;o<4;o++) acc2[i][o]=0ull;
#pragma unroll 4
        for (int c=0;c<64;c++){
            ulonglong2 a01 = *(const ulonglong2*)&h1T[c*136 + ty*8];
            ulonglong2 a23 = *(const ulonglong2*)&h1T[c*136 + ty*8 + 4];
            float4 wv = *(const float4*)&w1s[c*64 + tx*4];
            unsigned long long bs0 = splat2(wv.x), bs1 = splat2(wv.y),
                               bs2 = splat2(wv.z), bs3 = splat2(wv.w);
            unsigned long long av[4] = {a01.x, a01.y, a23.x, a23.y};
#pragma unroll
            for (int i=0;i<4;i++){
                fma2(acc2[i][0], av[i], bs0);
                fma2(acc2[i][1], av[i], bs1);
                fma2(acc2[i][2], av[i], bs2);
                fma2(acc2[i][3], av[i], bs3);
            }
        }
        __syncthreads();
#pragma unroll
        for (int i=0;i<4;i++){
            int m = ty*8 + i*2;
#pragma unroll
            for (int o=0;o<4;o++){
                float lo, hi; unpack2(acc2[i][o], lo, hi);
                float bias = b1s[tx*4+o];
                h1T[(tx*4+o)*136 + m]     = leaky(lo + bias);
                h1T[(tx*4+o)*136 + m + 1] = leaky(hi + bias);
            }
        }
    }
    __syncthreads();

    { // stage C: M=128 N=128 K=64, f32x2, two o-halves of 4
#pragma unroll
        for (int h = 0; h < 2; h++){
            unsigned long long acc2[4][4];
#pragma unroll
            for (int i=0;i<4;i++)
#pragma unroll
                for (int o=0;o<4;o++) acc2[i][o]=0ull;
#pragma unroll 4
            for (int c=0;c<64;c++){
                ulonglong2 a01 = *(const ulonglong2*)&h1T[c*136 + ty*8];
                ulonglong2 a23 = *(const ulonglong2*)&h1T[c*136 + ty*8 + 4];
                float4 wv = *(const float4*)&w2s[c*128 + tx*8 + h*4];
                unsigned long long bs0 = splat2(wv.x), bs1 = splat2(wv.y),
                                   bs2 = splat2(wv.z), bs3 = splat2(wv.w);
                unsigned long long av[4] = {a01.x, a01.y, a23.x, a23.y};
#pragma unroll
                for (int i=0;i<4;i++){
                    fma2(acc2[i][0], av[i], bs0);
                    fma2(acc2[i][1], av[i], bs1);
                    fma2(acc2[i][2], av[i], bs2);
                    fma2(acc2[i][3], av[i], bs3);
                }
            }
#pragma unroll
            for (int o=0;o<4;o++){
                float bias = b2s[tx*8 + h*4 + o];
                float pm = -3.4e38f;
#pragma unroll
                for (int i=0;i<4;i++){
                    float lo, hi; unpack2(acc2[i][o], lo, hi);
                    pm = fmaxf(pm, leaky(lo + bias));
                    pm = fmaxf(pm, leaky(hi + bias));
                }
                red[ty*128 + tx*8 + h*4 + o] = pm;
            }
        }
    }
    __syncthreads();

    for (int e=tid; e<1024; e+=256){
        int o = e & 127;
        int p = e >> 7;
        float v = fmaxf(red[(2*p)*128 + o], red[(2*p+1)*128 + o]);
        out[((long)(b*128 + o))*NP + n0 + p] = v;
    }
}

extern "C" void kernel_launch(void* const* d_in, const int* in_sizes, int n_in,
                              void* d_out, int out_size){
    const float* feat = (const float*)d_in[0];
    const float* pos  = (const float*)d_in[1];
    const float* Wn   = (const float*)d_in[2];
    const float* bn   = (const float*)d_in[3];
    const float* We   = (const float*)d_in[4];
    const float* be   = (const float*)d_in[5];
    const float* W1   = (const float*)d_in[6];
    const float* b1   = (const float*)d_in[7];
    const float* W2   = (const float*)d_in[8];
    const float* b2   = (const float*)d_in[9];
    float* out = (float*)d_out;

    cudaFuncSetAttribute(u_kernel,  cudaFuncAttributeMaxDynamicSharedMemorySize, 65536);
    cudaFuncSetAttribute(edge_main, cudaFuncAttributeMaxDynamicSharedMemorySize, 98304);

    prep_kernel<<<80,256>>>(Wn, We, W1, W2);
    knn_pass1<<<512,256>>>(pos);
    knn_pass2<<<1024,256>>>(pos);
    knn_pass3<<<2048,256>>>(pos);
    u_kernel<<<128,256,65536>>>(feat);
    edge_main<<<2048,256,96000>>>(bn, be, b1, b2, out);
}

// round 14
// speedup vs baseline: 4.6714x; 1.3110x over previous
#include <cuda_runtime.h>
#include <cuda_bf16.h>

#define NP 8192
#define NQ (2*NP)

__device__ __align__(16) float g_U[NQ*128];
__device__ float g_cmin[NQ*16];
__device__ unsigned long long g_surv[(long)NQ*16*32];
__device__ int   g_scnt[NQ*16];
__device__ int   g_knn[NQ*16];
__device__ __align__(16) float g_wu [64*128];
__device__ __align__(16) unsigned g_w1h[2048];   // [64 rows][32 words] bf16x2
__device__ __align__(16) unsigned g_w1l[2048];
__device__ __align__(16) unsigned g_w2h[4096];   // [128 rows][32 words]
__device__ __align__(16) unsigned g_w2l[4096];

__device__ __forceinline__ float leaky(float v){ return fmaxf(v, 0.2f*v); }
__device__ __forceinline__ float distp(float xi,float yi,float zi,const float4 c){
    return fmaf(zi,c.z,fmaf(yi,c.y,fmaf(xi,c.x,c.w)));
}
__device__ __forceinline__ unsigned int okey(float d){
    unsigned int u = __float_as_uint(d);
    u ^= ((unsigned int)((int)u >> 31)) | 0x80000000u;
    return u;
}
__device__ __forceinline__ unsigned long long umin64(unsigned long long a, unsigned long long b){
    return a < b ? a : b;
}
__device__ __forceinline__ void split2(float x0, float x1, unsigned &hi, unsigned &lo){
    __nv_bfloat16 h0 = __float2bfloat16(x0), h1 = __float2bfloat16(x1);
    hi = (unsigned)__bfloat16_as_ushort(h0) | ((unsigned)__bfloat16_as_ushort(h1) << 16);
    lo = (unsigned)__bfloat16_as_ushort(__float2bfloat16(x0 - __bfloat162float(h0))) |
         ((unsigned)__bfloat16_as_ushort(__float2bfloat16(x1 - __bfloat162float(h1))) << 16);
}
__device__ __forceinline__ void mma16816(float* d, unsigned a0, unsigned a1, unsigned a2, unsigned a3,
                                         unsigned b0, unsigned b1){
    asm volatile("mma.sync.aligned.m16n8k16.row.col.f32.bf16.bf16.f32 "
        "{%0,%1,%2,%3},{%4,%5,%6,%7},{%8,%9},{%0,%1,%2,%3};"
        : "+f"(d[0]), "+f"(d[1]), "+f"(d[2]), "+f"(d[3])
        : "r"(a0), "r"(a1), "r"(a2), "r"(a3), "r"(b0), "r"(b1));
}

// ---------------- prep: fp32 wu + bf16 hi/lo packed weight words ----------------
__global__ void prep_kernel(const float* __restrict__ Wn, const float* __restrict__ We,
                            const float* __restrict__ W1, const float* __restrict__ W2){
    int i = blockIdx.x*blockDim.x + threadIdx.x;
    if (i < 8192){
        int c = i >> 7, o = i & 127;
        g_wu[i] = (o < 64) ? Wn[o*64 + c] : We[(o-64)*64 + c];
    } else if (i < 10240){
        int j = i - 8192; int o = j >> 5, cw = j & 31;
        float w0 = W1[o*64 + cw*2], w1v = W1[o*64 + cw*2 + 1];
        unsigned hi, lo; split2(w0, w1v, hi, lo);
        g_w1h[j] = hi; g_w1l[j] = lo;
    } else if (i < 14336){
        int j = i - 10240; int o = j >> 5, cw = j & 31;
        float w0 = W2[o*64 + cw*2], w1v = W2[o*64 + cw*2 + 1];
        unsigned hi, lo; split2(w0, w1v, hi, lo);
        g_w2h[j] = hi; g_w2l[j] = lo;
    }
}

// ---------- KNN pass 1 ----------
__global__ void knn_pass1(const float* __restrict__ pos){
    __shared__ float4 tile[256];
    int bx = blockIdx.x;
    int b  = bx >> 8;
    int r  = bx & 255;
    int eighth = r >> 5;
    int n  = (r & 31)*256 + threadIdx.x;
    const float* pb = pos + b*NP*3;
    float xi = pb[n*3+0], yi = pb[n*3+1], zi = pb[n*3+2];
    long obase = ((long)(b*NP + n))*16 + eighth*2;

#pragma unroll
    for (int c2 = 0; c2 < 2; c2++){
        float mA = 3.4e38f, mB = 3.4e38f;
#pragma unroll
        for (int t2 = 0; t2 < 2; t2++){
            int jb = eighth*1024 + c2*512 + t2*256;
            int j  = jb + threadIdx.x;
            float x = pb[j*3+0], y = pb[j*3+1], z = pb[j*3+2];
            float sq = x*x; sq = fmaf(y,y,sq); sq = fmaf(z,z,sq);
            __syncthreads();
            tile[threadIdx.x] = make_float4(-2.0f*x, -2.0f*y, -2.0f*z, sq);
            __syncthreads();
#pragma unroll 8
            for (int jj = 0; jj < 256; jj += 4){
                float d0 = distp(xi,yi,zi, tile[jj+0]);
                float d1 = distp(xi,yi,zi, tile[jj+1]);
                float d2 = distp(xi,yi,zi, tile[jj+2]);
                float d3 = distp(xi,yi,zi, tile[jj+3]);
                mA = fminf(mA, fminf(d0,d1));
                mB = fminf(mB, fminf(d2,d3));
            }
        }
        g_cmin[obase + c2] = fminf(mA, mB);
    }
}

// ---------- KNN pass 2 ----------
__global__ void knn_pass2(const float* __restrict__ pos){
    __shared__ float4 tile[256];
    int bx  = blockIdx.x;
    int seg = bx & 15;
    int q   = (bx >> 4)*256 + threadIdx.x;
    int b   = q >> 13;
    int n   = q & 8191;
    const float* pb = pos + b*NP*3;
    float xi = pb[n*3+0], yi = pb[n*3+1], zi = pb[n*3+2];

    float T0 = -3.4e38f;
#pragma unroll
    for (int s = 0; s < 16; s++) T0 = fmaxf(T0, g_cmin[(long)q*16 + s]);

    unsigned long long* sv = &g_surv[((long)q*16 + seg)*32];
    int c = 0;
#pragma unroll
    for (int t = 0; t < 2; t++){
        int jb = seg*512 + t*256;
        int j  = jb + threadIdx.x;
        float x = pb[j*3+0], y = pb[j*3+1], z = pb[j*3+2];
        float sq = x*x; sq = fmaf(y,y,sq); sq = fmaf(z,z,sq);
        __syncthreads();
        tile[threadIdx.x] = make_float4(-2.0f*x, -2.0f*y, -2.0f*z, sq);
        __syncthreads();
        for (int jj = 0; jj < 256; jj += 4){
            float d0 = distp(xi,yi,zi, tile[jj+0]);
            float d1 = distp(xi,yi,zi, tile[jj+1]);
            float d2 = distp(xi,yi,zi, tile[jj+2]);
            float d3 = distp(xi,yi,zi, tile[jj+3]);
            float mn = fminf(fminf(d0,d1), fminf(d2,d3));
            if (mn <= T0){
                float dd[4] = {d0,d1,d2,d3};
#pragma unroll
                for (int u = 0; u < 4; u++){
                    if (dd[u] <= T0 && c < 32){
                        sv[c] = ((unsigned long long)okey(dd[u]) << 32) | (unsigned int)(jb + jj + u);
                        c++;
                    }
                }
            }
        }
    }
    g_scnt[(long)q*16 + seg] = c;
}

// ---------- KNN pass 3 ----------
__global__ void knn_pass3(const float* __restrict__ pos){
    int w    = threadIdx.x >> 5;
    int lane = threadIdx.x & 31;
    int q    = blockIdx.x*8 + w;

    int cs = (lane < 16) ? g_scnt[(long)q*16 + lane] : 0;
    unsigned ovfm = __ballot_sync(0xffffffff, lane < 16 && cs >= 32);
    int pre = cs;
#pragma unroll
    for (int o = 1; o < 16; o <<= 1){
        int v = __shfl_up_sync(0xffffffff, pre, o);
        if (lane >= o) pre += v;
    }
    int ip[16];
#pragma unroll
    for (int s = 0; s < 16; s++) ip[s] = __shfl_sync(0xffffffff, pre, s);
    int ctot = ip[15];

    if (!ovfm && ctot <= 256){
        unsigned long long k[8];
#pragma unroll
        for (int u = 0; u < 8; u++){
            int t = lane + u*32;
            unsigned long long key = ~0ull;
            if (t < ctot){
                int s = 0, base = 0;
#pragma unroll
                for (int kk = 0; kk < 15; kk++){
                    if (t >= ip[kk]){ s = kk+1; base = ip[kk]; }
                }
                key = g_surv[((long)q*16 + s)*32 + (t - base)];
            }
            k[u] = key;
        }
        if (ctot <= 128){
            for (int r = 0; r < 16; r++){
                unsigned long long best = umin64(umin64(k[0],k[1]), umin64(k[2],k[3]));
                unsigned long long rb = best;
#pragma unroll
                for (int o = 16; o; o >>= 1)
                    rb = umin64(rb, __shfl_down_sync(0xffffffff, rb, o));
                rb = __shfl_sync(0xffffffff, rb, 0);
                if (lane == 0) g_knn[(long)q*16 + r] = (int)(rb & 0xffffffffull);
                if (best == rb){
#pragma unroll
                    for (int u = 0; u < 4; u++) if (k[u] == rb) k[u] = ~0ull;
                }
            }
        } else {
            for (int r = 0; r < 16; r++){
                unsigned long long best = k[0];
#pragma unroll
                for (int u = 1; u < 8; u++) best = umin64(best, k[u]);
                unsigned long long rb = best;
#pragma unroll
                for (int o = 16; o; o >>= 1)
                    rb = umin64(rb, __shfl_down_sync(0xffffffff, rb, o));
                rb = __shfl_sync(0xffffffff, rb, 0);
                if (lane == 0) g_knn[(long)q*16 + r] = (int)(rb & 0xffffffffull);
                if (best == rb){
#pragma unroll
                    for (int u = 0; u < 8; u++) if (k[u] == rb) k[u] = ~0ull;
                }
            }
        }
    } else if (lane == 0){
        int b = q >> 13, n = q & 8191;
        const float* pb = pos + b*NP*3;
        float xi = pb[n*3+0], yi = pb[n*3+1], zi = pb[n*3+2];
        unsigned long long bk[16];
#pragma unroll
        for (int s = 0; s < 16; s++) bk[s] = ~0ull;
        unsigned long long worst = ~0ull; int ws = 0;
        for (int j = 0; j < NP; j++){
            float x = pb[j*3+0], y = pb[j*3+1], z = pb[j*3+2];
            float sq = x*x; sq = fmaf(y,y,sq); sq = fmaf(z,z,sq);
            float d = fmaf(zi,-2.0f*z, fmaf(yi,-2.0f*y, fmaf(xi,-2.0f*x, sq)));
            unsigned long long key = ((unsigned long long)okey(d) << 32) | (unsigned int)j;
            if (key < worst){
                bk[ws] = key;
                worst = bk[0]; ws = 0;
                for (int s = 1; s < 16; s++) if (bk[s] > worst){ worst = bk[s]; ws = s; }
            }
        }
        for (int rr = 0; rr < 16; rr++){
            unsigned long long best = ~0ull; int bj = 0;
            for (int s = 0; s < 16; s++) if (bk[s] < best){ best = bk[s]; bj = s; }
            bk[bj] = ~0ull;
            g_knn[(long)q*16 + rr] = (int)(best & 0xffffffffull);
        }
    }
}

// ---------------- U = [W_node; W_edge] * feat ----------------
__global__ void u_kernel(const float* __restrict__ feat){
    extern __shared__ float smC[];
    float* fs = smC;
    float* ws = smC + 64*128;
    int q0 = blockIdx.x*128;
    int b  = q0 >> 13;
    int n0 = q0 & 8191;
    for (int i=threadIdx.x; i<64*128; i+=256){
        int c = i>>7, nn = i&127;
        fs[i] = feat[((long)(b*64 + c))*NP + n0 + nn];
        ws[i] = g_wu[i];
    }
    __syncthreads();
    int tx = threadIdx.x & 15, ty = threadIdx.x >> 4;
    float acc[8][8];
#pragma unroll
    for (int i=0;i<8;i++)
#pragma unroll
        for (int j=0;j<8;j++) acc[i][j]=0.f;
#pragma unroll 4
    for (int c=0;c<64;c++){
        float4 a0 = *(const float4*)&fs[c*128 + ty*8];
        float4 a1 = *(const float4*)&fs[c*128 + ty*8 + 4];
        float4 w0 = *(const float4*)&ws[c*128 + tx*8];
        float4 w1 = *(const float4*)&ws[c*128 + tx*8 + 4];
        float av[8] = {a0.x,a0.y,a0.z,a0.w,a1.x,a1.y,a1.z,a1.w};
        float bv[8] = {w0.x,w0.y,w0.z,w0.w,w1.x,w1.y,w1.z,w1.w};
#pragma unroll
        for (int i=0;i<8;i++)
#pragma unroll
            for (int j=0;j<8;j++) acc[i][j] = fmaf(av[i], bv[j], acc[i][j]);
    }
#pragma unroll
    for (int i=0;i<8;i++){
        long q = q0 + ty*8 + i;
        float* r = &g_U[q*128 + tx*8];
        *(float4*)r     = make_float4(acc[i][0],acc[i][1],acc[i][2],acc[i][3]);
        *(float4*)(r+4) = make_float4(acc[i][4],acc[i][5],acc[i][6],acc[i][7]);
    }
}

// ---------------- edge_main: HMMA mma.sync, 3xBF16 split, warp-local pipeline ----------------
// rows padded to 36 words (72 bf16)
#define SM_IDX  0       // 128 int (512 B)
#define SM_BNS  512
#define SM_BES  768
#define SM_B1S  1024
#define SM_B2S  1280    // 128 f (512 B)
#define SM_HH   2048    // 128*36 words = 18432 B
#define SM_HL   20480
#define SM_W1H  38912   // 64*36 = 9216 B
#define SM_W1L  48128
#define SM_W2H  57344   // 128*36 = 18432 B
#define SM_W2L  75776
#define SM_TOT  94208

__global__ void __launch_bounds__(256, 2)
edge_main(const float* __restrict__ bn,  const float* __restrict__ be,
          const float* __restrict__ vb1, const float* __restrict__ vb2,
          float* __restrict__ out){
    extern __shared__ char smc[];
    int tid = threadIdx.x;
    int q0 = blockIdx.x*8;
    int b  = q0 >> 13;
    int n0 = q0 & 8191;

    float* bns = (float*)(smc + SM_BNS);
    float* bes = (float*)(smc + SM_BES);
    float* b1s = (float*)(smc + SM_B1S);
    float* b2s = (float*)(smc + SM_B2S);
    int*  idxs = (int*)  (smc + SM_IDX);
    unsigned* HH  = (unsigned*)(smc + SM_HH);
    unsigned* HL  = (unsigned*)(smc + SM_HL);
    unsigned* W1H = (unsigned*)(smc + SM_W1H);
    unsigned* W1L = (unsigned*)(smc + SM_W1L);
    unsigned* W2H = (unsigned*)(smc + SM_W2H);
    unsigned* W2L = (unsigned*)(smc + SM_W2L);

    // stage weights into padded rows
    for (int i=tid;i<2048;i+=256){ int rr=i>>5, ww=i&31; W1H[rr*36+ww]=g_w1h[i]; W1L[rr*36+ww]=g_w1l[i]; }
    for (int i=tid;i<4096;i+=256){ int rr=i>>5, ww=i&31; W2H[rr*36+ww]=g_w2h[i]; W2L[rr*36+ww]=g_w2l[i]; }
    if (tid<64){ bns[tid]=bn[tid]; bes[tid]=be[tid]; b1s[tid]=vb1[tid]; }
    if (tid<128) b2s[tid]=vb2[tid];
    if (tid<128) idxs[tid] = g_knn[(long)q0*16 + tid];
    __syncthreads();

    // ---- stage A: gather + layer1 -> HH/HL [m][64] bf16 hi/lo ----
    {
        int m  = tid >> 1;
        int jb = (tid & 1) * 32;
        int p  = m >> 4;
        int nb = idxs[m];
        const float* Ur = &g_U[(long)((b<<13) + nb)*128];
        const float* Uc = &g_U[(long)(q0 + p)*128 + 64];
#pragma unroll
        for (int v=0; v<8; v++){
            float4 un = *(const float4*)&Ur[jb + v*4];
            float4 ue = *(const float4*)&Ur[64 + jb + v*4];
            float unv[4] = {un.x,un.y,un.z,un.w};
            float uev[4] = {ue.x,ue.y,ue.z,ue.w};
            float hv[4];
#pragma unroll
            for (int e=0;e<4;e++){
                int j = jb + v*4 + e;
                float a = leaky(unv[e] + bns[j]);
                float c = leaky(uev[e] - Uc[j] + bes[j]);
                hv[e] = a + c;
            }
            int wbase = m*36 + (tid&1)*16 + v*2;
#pragma unroll
            for (int pr=0; pr<2; pr++){
                unsigned hi, lo;
                split2(hv[pr*2], hv[pr*2+1], hi, lo);
                HH[wbase+pr] = hi;
                HL[wbase+pr] = lo;
            }
        }
    }
    __syncwarp();

    int w    = tid >> 5;
    int lane = tid & 31;
    int g    = lane >> 2;
    int t    = lane & 3;
    int m0   = w*16;

    // ---- stage B: h2[16 x 64] = leaky(W1 * h1 + b1), 3-pass bf16 split ----
    {
        float dB[8][4];
#pragma unroll
        for (int nt=0; nt<8; nt++)
#pragma unroll
            for (int e=0;e<4;e++) dB[nt][e]=0.f;

        const unsigned* Asrc[3] = {HH, HH, HL};
        const unsigned* Bsrc[3] = {W1H, W1L, W1H};
#pragma unroll
        for (int ps=0; ps<3; ps++){
            const unsigned* A = Asrc[ps];
            const unsigned* B = Bsrc[ps];
#pragma unroll
            for (int k=0; k<4; k++){
                int ab = (m0+g)*36 + k*8 + t;
                unsigned a0 = A[ab], a1 = A[ab+8*36], a2 = A[ab+4], a3 = A[ab+8*36+4];
#pragma unroll
                for (int nt=0; nt<8; nt++){
                    int bb = (nt*8+g)*36 + k*8 + t;
                    mma16816(dB[nt], a0,a1,a2,a3, B[bb], B[bb+4]);
                }
            }
        }
        __syncwarp();
        // writeback h2 -> HH/HL (same rows this warp owns)
#pragma unroll
        for (int nt=0; nt<8; nt++){
            int o0 = nt*8 + 2*t;
            float bi0 = b1s[o0], bi1 = b1s[o0+1];
            float v00 = leaky(dB[nt][0] + bi0), v01 = leaky(dB[nt][1] + bi1);
            float v10 = leaky(dB[nt][2] + bi0), v11 = leaky(dB[nt][3] + bi1);
            unsigned hi, lo;
            int wA = (m0+g)*36 + nt*4 + t;
            split2(v00, v01, hi, lo); HH[wA] = hi; HL[wA] = lo;
            int wB = (m0+g+8)*36 + nt*4 + t;
            split2(v10, v11, hi, lo); HH[wB] = hi; HL[wB] = lo;
        }
    }
    __syncwarp();

    // ---- stage C: h3[16 x 128] + k-max-pool ----
    {
        float dC[16][4];
#pragma unroll
        for (int nt=0; nt<16; nt++)
#pragma unroll
            for (int e=0;e<4;e++) dC[nt][e]=0.f;

        const unsigned* Asrc[3] = {HH, HH, HL};
        const unsigned* Bsrc[3] = {W2H, W2L, W2H};
#pragma unroll
        for (int ps=0; ps<3; ps++){
            const unsigned* A = Asrc[ps];
            const unsigned* B = Bsrc[ps];
#pragma unroll
            for (int k=0; k<4; k++){
                int ab = (m0+g)*36 + k*8 + t;
                unsigned a0 = A[ab], a1 = A[ab+8*36], a2 = A[ab+4], a3 = A[ab+8*36+4];
#pragma unroll
                for (int nt=0; nt<16; nt++){
                    int bb = (nt*8+g)*36 + k*8 + t;
                    mma16816(dC[nt], a0,a1,a2,a3, B[bb], B[bb+4]);
                }
            }
        }

        // bias + leaky + max over this warp's 16 rows (one point), write out
#pragma unroll
        for (int nt=0; nt<16; nt++){
            int o0 = nt*8 + 2*t;
            float bi0 = b2s[o0], bi1 = b2s[o0+1];
            float c0 = fmaxf(leaky(dC[nt][0] + bi0), leaky(dC[nt][2] + bi0));
            float c1 = fmaxf(leaky(dC[nt][1] + bi1), leaky(dC[nt][3] + bi1));
#pragma unroll
            for (int o = 4; o <= 16; o <<= 1){
                c0 = fmaxf(c0, __shfl_xor_sync(0xffffffff, c0, o));
                c1 = fmaxf(c1, __shfl_xor_sync(0xffffffff, c1, o));
            }
            if (g == 0){
                out[((long)(b*128 + o0  ))*NP + n0 + w] = c0;
                out[((long)(b*128 + o0+1))*NP + n0 + w] = c1;
            }
        }
    }
}

extern "C" void kernel_launch(void* const* d_in, const int* in_sizes, int n_in,
                              void* d_out, int out_size){
    const float* feat = (const float*)d_in[0];
    const float* pos  = (const float*)d_in[1];
    const float* Wn   = (const float*)d_in[2];
    const float* bn   = (const float*)d_in[3];
    const float* We   = (const float*)d_in[4];
    const float* be   = (const float*)d_in[5];
    const float* W1   = (const float*)d_in[6];
    const float* b1   = (const float*)d_in[7];
    const float* W2   = (const float*)d_in[8];
    const float* b2   = (const float*)d_in[9];
    float* out = (float*)d_out;

    cudaFuncSetAttribute(u_kernel,  cudaFuncAttributeMaxDynamicSharedMemorySize, 65536);
    cudaFuncSetAttribute(edge_main, cudaFuncAttributeMaxDynamicSharedMemorySize, SM_TOT);

    prep_kernel<<<80,256>>>(Wn, We, W1, W2);
    knn_pass1<<<512,256>>>(pos);
    knn_pass2<<<1024,256>>>(pos);
    knn_pass3<<<2048,256>>>(pos);
    u_kernel<<<128,256,65536>>>(feat);
    edge_main<<<2048,256,SM_TOT>>>(bn, be, b1, b2, out);
}

// round 15
// speedup vs baseline: 5.0976x; 1.0912x over previous
#include <cuda_runtime.h>
#include <cuda_bf16.h>

#define NP 8192
#define NQ (2*NP)

__device__ __align__(16) float g_U[NQ*128];
__device__ float g_cmin[NQ*16];
__device__ unsigned long long g_surv[(long)NQ*16*32];
__device__ int   g_scnt[NQ*16];
__device__ int   g_knn[NQ*16];
__device__ __align__(16) float g_wu [64*128];
__device__ __align__(16) unsigned g_w1h[2048];
__device__ __align__(16) unsigned g_w1l[2048];
__device__ __align__(16) unsigned g_w2h[4096];
__device__ __align__(16) unsigned g_w2l[4096];

__device__ __forceinline__ float leaky(float v){ return fmaxf(v, 0.2f*v); }
__device__ __forceinline__ float distp(float xi,float yi,float zi,const float4 c){
    return fmaf(zi,c.z,fmaf(yi,c.y,fmaf(xi,c.x,c.w)));
}
__device__ __forceinline__ unsigned int okey(float d){
    unsigned int u = __float_as_uint(d);
    u ^= ((unsigned int)((int)u >> 31)) | 0x80000000u;
    return u;
}
__device__ __forceinline__ unsigned long long umin64(unsigned long long a, unsigned long long b){
    return a < b ? a : b;
}
__device__ __forceinline__ void split2(float x0, float x1, unsigned &hi, unsigned &lo){
    __nv_bfloat16 h0 = __float2bfloat16(x0), h1 = __float2bfloat16(x1);
    hi = (unsigned)__bfloat16_as_ushort(h0) | ((unsigned)__bfloat16_as_ushort(h1) << 16);
    lo = (unsigned)__bfloat16_as_ushort(__float2bfloat16(x0 - __bfloat162float(h0))) |
         ((unsigned)__bfloat16_as_ushort(__float2bfloat16(x1 - __bfloat162float(h1))) << 16);
}
__device__ __forceinline__ void mma16816(float* d, unsigned a0, unsigned a1, unsigned a2, unsigned a3,
                                         unsigned b0, unsigned b1){
    asm volatile("mma.sync.aligned.m16n8k16.row.col.f32.bf16.bf16.f32 "
        "{%0,%1,%2,%3},{%4,%5,%6,%7},{%8,%9},{%0,%1,%2,%3};"
        : "+f"(d[0]), "+f"(d[1]), "+f"(d[2]), "+f"(d[3])
        : "r"(a0), "r"(a1), "r"(a2), "r"(a3), "r"(b0), "r"(b1));
}

// ---------------- prep ----------------
__global__ void prep_kernel(const float* __restrict__ Wn, const float* __restrict__ We,
                            const float* __restrict__ W1, const float* __restrict__ W2){
    int i = blockIdx.x*blockDim.x + threadIdx.x;
    if (i < 8192){
        int c = i >> 7, o = i & 127;
        g_wu[i] = (o < 64) ? Wn[o*64 + c] : We[(o-64)*64 + c];
    } else if (i < 10240){
        int j = i - 8192; int o = j >> 5, cw = j & 31;
        unsigned hi, lo; split2(W1[o*64 + cw*2], W1[o*64 + cw*2 + 1], hi, lo);
        g_w1h[j] = hi; g_w1l[j] = lo;
    } else if (i < 14336){
        int j = i - 10240; int o = j >> 5, cw = j & 31;
        unsigned hi, lo; split2(W2[o*64 + cw*2], W2[o*64 + cw*2 + 1], hi, lo);
        g_w2h[j] = hi; g_w2l[j] = lo;
    }
}

// ---------- KNN pass 1 ----------
__global__ void knn_pass1(const float* __restrict__ pos){
    __shared__ float4 tile[256];
    int bx = blockIdx.x;
    int b  = bx >> 8;
    int r  = bx & 255;
    int eighth = r >> 5;
    int n  = (r & 31)*256 + threadIdx.x;
    const float* pb = pos + b*NP*3;
    float xi = pb[n*3+0], yi = pb[n*3+1], zi = pb[n*3+2];
    long obase = ((long)(b*NP + n))*16 + eighth*2;

#pragma unroll
    for (int c2 = 0; c2 < 2; c2++){
        float mA = 3.4e38f, mB = 3.4e38f;
#pragma unroll
        for (int t2 = 0; t2 < 2; t2++){
            int jb = eighth*1024 + c2*512 + t2*256;
            int j  = jb + threadIdx.x;
            float x = pb[j*3+0], y = pb[j*3+1], z = pb[j*3+2];
            float sq = x*x; sq = fmaf(y,y,sq); sq = fmaf(z,z,sq);
            __syncthreads();
            tile[threadIdx.x] = make_float4(-2.0f*x, -2.0f*y, -2.0f*z, sq);
            __syncthreads();
#pragma unroll 8
            for (int jj = 0; jj < 256; jj += 4){
                float d0 = distp(xi,yi,zi, tile[jj+0]);
                float d1 = distp(xi,yi,zi, tile[jj+1]);
                float d2 = distp(xi,yi,zi, tile[jj+2]);
                float d3 = distp(xi,yi,zi, tile[jj+3]);
                mA = fminf(mA, fminf(d0,d1));
                mB = fminf(mB, fminf(d2,d3));
            }
        }
        g_cmin[obase + c2] = fminf(mA, mB);
    }
}

// ---------- KNN pass 2 ----------
__global__ void knn_pass2(const float* __restrict__ pos){
    __shared__ float4 tile[256];
    int bx  = blockIdx.x;
    int seg = bx & 15;
    int q   = (bx >> 4)*256 + threadIdx.x;
    int b   = q >> 13;
    int n   = q & 8191;
    const float* pb = pos + b*NP*3;
    float xi = pb[n*3+0], yi = pb[n*3+1], zi = pb[n*3+2];

    float T0 = -3.4e38f;
#pragma unroll
    for (int s = 0; s < 16; s++) T0 = fmaxf(T0, g_cmin[(long)q*16 + s]);

    unsigned long long* sv = &g_surv[((long)q*16 + seg)*32];
    int c = 0;
#pragma unroll
    for (int t = 0; t < 2; t++){
        int jb = seg*512 + t*256;
        int j  = jb + threadIdx.x;
        float x = pb[j*3+0], y = pb[j*3+1], z = pb[j*3+2];
        float sq = x*x; sq = fmaf(y,y,sq); sq = fmaf(z,z,sq);
        __syncthreads();
        tile[threadIdx.x] = make_float4(-2.0f*x, -2.0f*y, -2.0f*z, sq);
        __syncthreads();
        for (int jj = 0; jj < 256; jj += 4){
            float d0 = distp(xi,yi,zi, tile[jj+0]);
            float d1 = distp(xi,yi,zi, tile[jj+1]);
            float d2 = distp(xi,yi,zi, tile[jj+2]);
            float d3 = distp(xi,yi,zi, tile[jj+3]);
            float mn = fminf(fminf(d0,d1), fminf(d2,d3));
            if (mn <= T0){
                float dd[4] = {d0,d1,d2,d3};
#pragma unroll
                for (int u = 0; u < 4; u++){
                    if (dd[u] <= T0 && c < 32){
                        sv[c] = ((unsigned long long)okey(dd[u]) << 32) | (unsigned int)(jb + jj + u);
                        c++;
                    }
                }
            }
        }
    }
    g_scnt[(long)q*16 + seg] = c;
}

// ---------- KNN pass 3 ----------
__global__ void knn_pass3(const float* __restrict__ pos){
    int w    = threadIdx.x >> 5;
    int lane = threadIdx.x & 31;
    int q    = blockIdx.x*8 + w;

    int cs = (lane < 16) ? g_scnt[(long)q*16 + lane] : 0;
    unsigned ovfm = __ballot_sync(0xffffffff, lane < 16 && cs >= 32);
    int pre = cs;
#pragma unroll
    for (int o = 1; o < 16; o <<= 1){
        int v = __shfl_up_sync(0xffffffff, pre, o);
        if (lane >= o) pre += v;
    }
    int ip[16];
#pragma unroll
    for (int s = 0; s < 16; s++) ip[s] = __shfl_sync(0xffffffff, pre, s);
    int ctot = ip[15];

    if (!ovfm && ctot <= 256){
        unsigned long long k[8];
#pragma unroll
        for (int u = 0; u < 8; u++){
            int t = lane + u*32;
            unsigned long long key = ~0ull;
            if (t < ctot){
                int s = 0, base = 0;
#pragma unroll
                for (int kk = 0; kk < 15; kk++){
                    if (t >= ip[kk]){ s = kk+1; base = ip[kk]; }
                }
                key = g_surv[((long)q*16 + s)*32 + (t - base)];
            }
            k[u] = key;
        }
        if (ctot <= 64){
            for (int r = 0; r < 16; r++){
                unsigned long long best = umin64(k[0], k[1]);
                unsigned long long rb = best;
#pragma unroll
                for (int o = 16; o; o >>= 1)
                    rb = umin64(rb, __shfl_down_sync(0xffffffff, rb, o));
                rb = __shfl_sync(0xffffffff, rb, 0);
                if (lane == 0) g_knn[(long)q*16 + r] = (int)(rb & 0xffffffffull);
                if (best == rb){
                    if (k[0] == rb) k[0] = ~0ull;
                    if (k[1] == rb) k[1] = ~0ull;
                }
            }
        } else if (ctot <= 128){
            for (int r = 0; r < 16; r++){
                unsigned long long best = umin64(umin64(k[0],k[1]), umin64(k[2],k[3]));
                unsigned long long rb = best;
#pragma unroll
                for (int o = 16; o; o >>= 1)
                    rb = umin64(rb, __shfl_down_sync(0xffffffff, rb, o));
                rb = __shfl_sync(0xffffffff, rb, 0);
                if (lane == 0) g_knn[(long)q*16 + r] = (int)(rb & 0xffffffffull);
                if (best == rb){
#pragma unroll
                    for (int u = 0; u < 4; u++) if (k[u] == rb) k[u] = ~0ull;
                }
            }
        } else {
            for (int r = 0; r < 16; r++){
                unsigned long long best = k[0];
#pragma unroll
                for (int u = 1; u < 8; u++) best = umin64(best, k[u]);
                unsigned long long rb = best;
#pragma unroll
                for (int o = 16; o; o >>= 1)
                    rb = umin64(rb, __shfl_down_sync(0xffffffff, rb, o));
                rb = __shfl_sync(0xffffffff, rb, 0);
                if (lane == 0) g_knn[(long)q*16 + r] = (int)(rb & 0xffffffffull);
                if (best == rb){
#pragma unroll
                    for (int u = 0; u < 8; u++) if (k[u] == rb) k[u] = ~0ull;
                }
            }
        }
    } else if (lane == 0){
        int b = q >> 13, n = q & 8191;
        const float* pb = pos + b*NP*3;
        float xi = pb[n*3+0], yi = pb[n*3+1], zi = pb[n*3+2];
        unsigned long long bk[16];
#pragma unroll
        for (int s = 0; s < 16; s++) bk[s] = ~0ull;
        unsigned long long worst = ~0ull; int ws = 0;
        for (int j = 0; j < NP; j++){
            float x = pb[j*3+0], y = pb[j*3+1], z = pb[j*3+2];
            float sq = x*x; sq = fmaf(y,y,sq); sq = fmaf(z,z,sq);
            float d = fmaf(zi,-2.0f*z, fmaf(yi,-2.0f*y, fmaf(xi,-2.0f*x, sq)));
            unsigned long long key = ((unsigned long long)okey(d) << 32) | (unsigned int)j;
            if (key < worst){
                bk[ws] = key;
                worst = bk[0]; ws = 0;
                for (int s = 1; s < 16; s++) if (bk[s] > worst){ worst = bk[s]; ws = s; }
            }
        }
        for (int rr = 0; rr < 16; rr++){
            unsigned long long best = ~0ull; int bj = 0;
            for (int s = 0; s < 16; s++) if (bk[s] < best){ best = bk[s]; bj = s; }
            bk[bj] = ~0ull;
            g_knn[(long)q*16 + rr] = (int)(best & 0xffffffffull);
        }
    }
}

// ---------------- U = [W_node; W_edge] * feat ----------------
__global__ void u_kernel(const float* __restrict__ feat){
    extern __shared__ float smC[];
    float* fs = smC;
    float* ws = smC + 64*128;
    int q0 = blockIdx.x*128;
    int b  = q0 >> 13;
    int n0 = q0 & 8191;
    for (int i=threadIdx.x; i<64*128; i+=256){
        int c = i>>7, nn = i&127;
        fs[i] = feat[((long)(b*64 + c))*NP + n0 + nn];
        ws[i] = g_wu[i];
    }
    __syncthreads();
    int tx = threadIdx.x & 15, ty = threadIdx.x >> 4;
    float acc[8][8];
#pragma unroll
    for (int i=0;i<8;i++)
#pragma unroll
        for (int j=0;j<8;j++) acc[i][j]=0.f;
#pragma unroll 4
    for (int c=0;c<64;c++){
        float4 a0 = *(const float4*)&fs[c*128 + ty*8];
        float4 a1 = *(const float4*)&fs[c*128 + ty*8 + 4];
        float4 w0 = *(const float4*)&ws[c*128 + tx*8];
        float4 w1 = *(const float4*)&ws[c*128 + tx*8 + 4];
        float av[8] = {a0.x,a0.y,a0.z,a0.w,a1.x,a1.y,a1.z,a1.w};
        float bv[8] = {w0.x,w0.y,w0.z,w0.w,w1.x,w1.y,w1.z,w1.w};
#pragma unroll
        for (int i=0;i<8;i++)
#pragma unroll
            for (int j=0;j<8;j++) acc[i][j] = fmaf(av[i], bv[j], acc[i][j]);
    }
#pragma unroll
    for (int i=0;i<8;i++){
        long q = q0 + ty*8 + i;
        float* r = &g_U[q*128 + tx*8];
        *(float4*)r     = make_float4(acc[i][0],acc[i][1],acc[i][2],acc[i][3]);
        *(float4*)(r+4) = make_float4(acc[i][4],acc[i][5],acc[i][6],acc[i][7]);
    }
}

// ---------------- edge_main: persistent blocks, HMMA 3xBF16 split ----------------
#define SM_IDX  0
#define SM_BNS  512
#define SM_BES  768
#define SM_B1S  1024
#define SM_B2S  1280
#define SM_HH   2048
#define SM_HL   20480
#define SM_W1H  38912
#define SM_W1L  48128
#define SM_W2H  57344
#define SM_W2L  75776
#define SM_TOT  94208
#define NTILE   2048

__global__ void __launch_bounds__(256, 2)
edge_main(const float* __restrict__ bn,  const float* __restrict__ be,
          const float* __restrict__ vb1, const float* __restrict__ vb2,
          float* __restrict__ out){
    extern __shared__ char smc[];
    int tid = threadIdx.x;

    float* bns = (float*)(smc + SM_BNS);
    float* bes = (float*)(smc + SM_BES);
    float* b1s = (float*)(smc + SM_B1S);
    float* b2s = (float*)(smc + SM_B2S);
    int*  idxs = (int*)  (smc + SM_IDX);
    unsigned* HH  = (unsigned*)(smc + SM_HH);
    unsigned* HL  = (unsigned*)(smc + SM_HL);
    unsigned* W1H = (unsigned*)(smc + SM_W1H);
    unsigned* W1L = (unsigned*)(smc + SM_W1L);
    unsigned* W2H = (unsigned*)(smc + SM_W2H);
    unsigned* W2L = (unsigned*)(smc + SM_W2L);

    // one-time staging
    for (int i=tid;i<2048;i+=256){ int rr=i>>5, ww=i&31; W1H[rr*36+ww]=g_w1h[i]; W1L[rr*36+ww]=g_w1l[i]; }
    for (int i=tid;i<4096;i+=256){ int rr=i>>5, ww=i&31; W2H[rr*36+ww]=g_w2h[i]; W2L[rr*36+ww]=g_w2l[i]; }
    if (tid<64){ bns[tid]=bn[tid]; bes[tid]=be[tid]; b1s[tid]=vb1[tid]; }
    if (tid<128) b2s[tid]=vb2[tid];

    int w    = tid >> 5;
    int lane = tid & 31;
    int g    = lane >> 2;
    int t    = lane & 3;
    int m0   = w*16;

    for (int tile = blockIdx.x; tile < NTILE; tile += gridDim.x){
        int q0 = tile*8;
        int b  = q0 >> 13;
        int n0 = q0 & 8191;

        __syncthreads();   // previous iteration fully done (idxs safe to overwrite)
        if (tid<128) idxs[tid] = g_knn[(long)q0*16 + tid];
        __syncthreads();

        { // stage A: gather + layer1 -> HH/HL
            int m  = tid >> 1;
            int jb = (tid & 1) * 32;
            int p  = m >> 4;
            int nb = idxs[m];
            const float* Ur = &g_U[(long)((b<<13) + nb)*128];
            const float* Uc = &g_U[(long)(q0 + p)*128 + 64];
#pragma unroll
            for (int v=0; v<8; v++){
                float4 un = *(const float4*)&Ur[jb + v*4];
                float4 ue = *(const float4*)&Ur[64 + jb + v*4];
                float unv[4] = {un.x,un.y,un.z,un.w};
                float uev[4] = {ue.x,ue.y,ue.z,ue.w};
                float hv[4];
#pragma unroll
                for (int e=0;e<4;e++){
                    int j = jb + v*4 + e;
                    float a = leaky(unv[e] + bns[j]);
                    float c = leaky(uev[e] - Uc[j] + bes[j]);
                    hv[e] = a + c;
                }
                int wbase = m*36 + (tid&1)*16 + v*2;
#pragma unroll
                for (int pr=0; pr<2; pr++){
                    unsigned hi, lo;
                    split2(hv[pr*2], hv[pr*2+1], hi, lo);
                    HH[wbase+pr] = hi;
                    HL[wbase+pr] = lo;
                }
            }
        }
        __syncwarp();

        { // stage B: h2 = leaky(W1*h1 + b1)
            float dB[8][4];
#pragma unroll
            for (int nt=0; nt<8; nt++)
#pragma unroll
                for (int e=0;e<4;e++) dB[nt][e]=0.f;

            const unsigned* Asrc[3] = {HH, HH, HL};
            const unsigned* Bsrc[3] = {W1H, W1L, W1H};
#pragma unroll
            for (int ps=0; ps<3; ps++){
                const unsigned* A = Asrc[ps];
                const unsigned* B = Bsrc[ps];
#pragma unroll
                for (int k=0; k<4; k++){
                    int ab = (m0+g)*36 + k*8 + t;
                    unsigned a0 = A[ab], a1 = A[ab+8*36], a2 = A[ab+4], a3 = A[ab+8*36+4];
#pragma unroll
                    for (int nt=0; nt<8; nt++){
                        int bb = (nt*8+g)*36 + k*8 + t;
                        mma16816(dB[nt], a0,a1,a2,a3, B[bb], B[bb+4]);
                    }
                }
            }
            __syncwarp();
#pragma unroll
            for (int nt=0; nt<8; nt++){
                int o0 = nt*8 + 2*t;
                float bi0 = b1s[o0], bi1 = b1s[o0+1];
                float v00 = leaky(dB[nt][0] + bi0), v01 = leaky(dB[nt][1] + bi1);
                float v10 = leaky(dB[nt][2] + bi0), v11 = leaky(dB[nt][3] + bi1);
                unsigned hi, lo;
                int wA = (m0+g)*36 + nt*4 + t;
                split2(v00, v01, hi, lo); HH[wA] = hi; HL[wA] = lo;
                int wB = (m0+g+8)*36 + nt*4 + t;
                split2(v10, v11, hi, lo); HH[wB] = hi; HL[wB] = lo;
            }
        }
        __syncwarp();

        { // stage C + maxpool
            float dC[16][4];
#pragma unroll
            for (int nt=0; nt<16; nt++)
#pragma unroll
                for (int e=0;e<4;e++) dC[nt][e]=0.f;

            const unsigned* Asrc[3] = {HH, HH, HL};
            const unsigned* Bsrc[3] = {W2H, W2L, W2H};
#pragma unroll
            for (int ps=0; ps<3; ps++){
                const unsigned* A = Asrc[ps];
                const unsigned* B = Bsrc[ps];
#pragma unroll
                for (int k=0; k<4; k++){
                    int ab = (m0+g)*36 + k*8 + t;
                    unsigned a0 = A[ab], a1 = A[ab+8*36], a2 = A[ab+4], a3 = A[ab+8*36+4];
#pragma unroll
                    for (int nt=0; nt<16; nt++){
                        int bb = (nt*8+g)*36 + k*8 + t;
                        mma16816(dC[nt], a0,a1,a2,a3, B[bb], B[bb+4]);
                    }
                }
            }

#pragma unroll
            for (int nt=0; nt<16; nt++){
                int o0 = nt*8 + 2*t;
                float bi0 = b2s[o0], bi1 = b2s[o0+1];
                float c0 = fmaxf(leaky(dC[nt][0] + bi0), leaky(dC[nt][2] + bi0));
                float c1 = fmaxf(leaky(dC[nt][1] + bi1), leaky(dC[nt][3] + bi1));
#pragma unroll
                for (int o = 4; o <= 16; o <<= 1){
                    c0 = fmaxf(c0, __shfl_xor_sync(0xffffffff, c0, o));
                    c1 = fmaxf(c1, __shfl_xor_sync(0xffffffff, c1, o));
                }
                if (g == 0){
                    out[((long)(b*128 + o0  ))*NP + n0 + w] = c0;
                    out[((long)(b*128 + o0+1))*NP + n0 + w] = c1;
                }
            }
        }
    }
}

extern "C" void kernel_launch(void* const* d_in, const int* in_sizes, int n_in,
                              void* d_out, int out_size){
    const float* feat = (const float*)d_in[0];
    const float* pos  = (const float*)d_in[1];
    const float* Wn   = (const float*)d_in[2];
    const float* bn   = (const float*)d_in[3];
    const float* We   = (const float*)d_in[4];
    const float* be   = (const float*)d_in[5];
    const float* W1   = (const float*)d_in[6];
    const float* b1   = (const float*)d_in[7];
    const float* W2   = (const float*)d_in[8];
    const float* b2   = (const float*)d_in[9];
    float* out = (float*)d_out;

    cudaFuncSetAttribute(u_kernel,  cudaFuncAttributeMaxDynamicSharedMemorySize, 65536);
    cudaFuncSetAttribute(edge_main, cudaFuncAttributeMaxDynamicSharedMemorySize, SM_TOT);

    prep_kernel<<<80,256>>>(Wn, We, W1, W2);
    knn_pass1<<<512,256>>>(pos);
    knn_pass2<<<1024,256>>>(pos);
    knn_pass3<<<2048,256>>>(pos);
    u_kernel<<<128,256,65536>>>(feat);
    edge_main<<<296,256,SM_TOT>>>(bn, be, b1, b2, out);
}